// round 1
// baseline (speedup 1.0000x reference)
#include <cuda_runtime.h>
#include <cstdint>

// ---------------------------------------------------------------------------
// LocalizedFiltering: two causal conv1d (ksize=2) layers over ragged batch,
// residual + RMSNorm, plus lf1/lf2 cache outputs.
//
// Reformulated as dense GEMMs (no recurrence, ksize=2):
//   O1[t] = W1_0 @ xprev(t) + W1_1 @ x[t] + b1
//   O2[t] = W2_0 @ o1prev(t) + W2_1 @ O1[t] + b2
//   out[t] = RMSNorm(O2[t] + x[t]) * gamma
// Boundary at sequence start p==0:
//   xprev  = (L==max_len) ? lf1_cache[b] : 0
//   o1prev = (L==max_len) ? lf2_cache[b] : b1 (+ W1_0@lf1 iff max_len-L==1)
// Output layout: [lf_output (total*E)] [lf1 (B*E)] [lf2 (B*H)]
// ---------------------------------------------------------------------------

#define MAX_TOTAL 24576
#define MAX_E     2048
#define MAX_H     1024
#define MAX_B     64

// scratch (static __device__ per harness rules: no cudaMalloc)
__device__ float g_W1T0[MAX_E * MAX_H];   // [k*H + n]  (K-major, k in [0,E))
__device__ float g_W1T1[MAX_E * MAX_H];
__device__ float g_W2T0[MAX_H * MAX_E];   // [k*E + n]  (k in [0,H))
__device__ float g_W2T1[MAX_H * MAX_E];
__device__ float g_O1  [(size_t)MAX_TOTAL * MAX_H];
__device__ float g_pre [(size_t)MAX_TOTAL * MAX_E];
__device__ float g_bndX [MAX_B * MAX_E];
__device__ float g_bndO1[MAX_B * MAX_H];
__device__ int   g_tokseq[MAX_TOTAL];

// ---------------------------------------------------------------------------
__global__ void pack_w_kernel(const float* __restrict__ w1,
                              const float* __restrict__ w2,
                              int E, int H)
{
    int stride = gridDim.x * blockDim.x;
    int idx = blockIdx.x * blockDim.x + threadIdx.x;
    int n1 = H * E;
    // w1: (H, E, 2) -> W1T{0,1}[k*H + o]
    for (int i = idx; i < n1; i += stride) {
        int o = i / E, k = i - o * E;
        size_t src = ((size_t)o * E + k) * 2;
        g_W1T0[(size_t)k * H + o] = w1[src + 0];
        g_W1T1[(size_t)k * H + o] = w1[src + 1];
    }
    // w2: (E, H, 2) -> W2T{0,1}[k*E + o]
    for (int i = idx; i < n1; i += stride) {
        int o = i / H, k = i - o * H;
        size_t src = ((size_t)o * H + k) * 2;
        g_W2T0[(size_t)k * E + o] = w2[src + 0];
        g_W2T1[(size_t)k * E + o] = w2[src + 1];
    }
}

__global__ void prep_tok_kernel(const int* __restrict__ start, int B, int total)
{
    int t = blockIdx.x * blockDim.x + threadIdx.x;
    if (t >= total) return;
    int lo = 0, hi = B - 1;
    while (lo < hi) {
        int mid = (lo + hi + 1) >> 1;
        if (start[mid] <= t) lo = mid; else hi = mid - 1;
    }
    g_tokseq[t] = lo;
}

__global__ void prep_bnd_kernel(const float* __restrict__ lf1,
                                const float* __restrict__ lf2,
                                const float* __restrict__ w1,
                                const float* __restrict__ b1,
                                const int*   __restrict__ lens,
                                const int*   __restrict__ maxlen_ptr,
                                int E, int H)
{
    int b = blockIdx.x;
    int L = lens[b];
    int ml = maxlen_ptr ? maxlen_ptr[0] : 4096;
    bool full = (L == ml);
    for (int i = threadIdx.x; i < E; i += blockDim.x)
        g_bndX[(size_t)b * E + i] = full ? lf1[(size_t)b * E + i] : 0.f;
    int s0 = ml - L;
    for (int n = threadIdx.x; n < H; n += blockDim.x) {
        float v;
        if (full) {
            v = lf2[(size_t)b * H + n];
        } else {
            v = b1[n];
            if (s0 == 1) { // prev padded position is s=0 which saw lf1_cache
                const float* wr = w1 + (size_t)n * E * 2;
                float acc = 0.f;
                for (int k = 0; k < E; k++) acc += wr[(size_t)k * 2] * lf1[(size_t)b * E + k];
                v += acc;
            }
        }
        g_bndO1[(size_t)b * H + n] = v;
    }
}

// ---------------------------------------------------------------------------
// Fused "shifted-pair" GEMM: C[t,n] = sum_k Aprev[t,k]*W0T[k,n] + Acur[t,k]*W1T[k,n]
//                                     + bias[n] (+ resid[t,n])
// Aprev row t = src[t-1] (or bnd[seq] at sequence start). BM=BN=128, BK=8.
// ---------------------------------------------------------------------------
template<bool ADD_RES>
__global__ __launch_bounds__(256, 2)
void conv_gemm_kernel(const float* __restrict__ src,
                      const float* __restrict__ bnd,
                      const float* __restrict__ W0T,
                      const float* __restrict__ W1T,
                      const float* __restrict__ bias,
                      const float* __restrict__ resid,
                      const int*   __restrict__ start,
                      int M, int N, int K,
                      float* __restrict__ Cout)
{
    const int BM = 128, BN = 128, BK = 8;
    __shared__ float Ap[BK][BM];
    __shared__ float Ac[BK][BM];
    __shared__ float B0s[BK][BN];
    __shared__ float B1s[BK][BN];

    const int m0 = blockIdx.y * BM;
    const int n0 = blockIdx.x * BN;
    const int tid = threadIdx.x;

    // A load assignment: 2 threads per row, 4 contiguous k each
    const int arow  = tid >> 1;
    const int akofs = (tid & 1) * 4;
    int t = m0 + arow;
    if (t >= M) t = M - 1;
    const float* aCur;
    const float* aPrev;
    {
        int b = g_tokseq[t];
        aCur  = src + (size_t)t * K;
        aPrev = (t == start[b]) ? (bnd + (size_t)b * K)
                                : (src + (size_t)(t - 1) * K);
    }
    // B load assignment: 8 k-rows x 128 n, one float4 per thread
    const int bk = tid >> 5;
    const int bn = (tid & 31) * 4;
    const float* b0p = W0T + (size_t)bk * N + n0 + bn;
    const float* b1p = W1T + (size_t)bk * N + n0 + bn;

    float acc[8][8];
    #pragma unroll
    for (int i = 0; i < 8; i++)
        #pragma unroll
        for (int j = 0; j < 8; j++) acc[i][j] = 0.f;

    const int tr = (tid >> 4) * 8;   // 0..120
    const int tc = (tid & 15) * 8;   // 0..120

    for (int kb = 0; kb < K; kb += BK) {
        float4 vc = *(const float4*)(aCur  + kb + akofs);
        float4 vp = *(const float4*)(aPrev + kb + akofs);
        Ac[akofs + 0][arow] = vc.x; Ac[akofs + 1][arow] = vc.y;
        Ac[akofs + 2][arow] = vc.z; Ac[akofs + 3][arow] = vc.w;
        Ap[akofs + 0][arow] = vp.x; Ap[akofs + 1][arow] = vp.y;
        Ap[akofs + 2][arow] = vp.z; Ap[akofs + 3][arow] = vp.w;
        *(float4*)&B0s[bk][bn] = *(const float4*)(b0p + (size_t)kb * N);
        *(float4*)&B1s[bk][bn] = *(const float4*)(b1p + (size_t)kb * N);
        __syncthreads();

        #pragma unroll
        for (int k = 0; k < BK; k++) {
            float rap[8], rac[8], rb0[8], rb1[8];
            *(float4*)(rap)     = *(float4*)&Ap[k][tr];
            *(float4*)(rap + 4) = *(float4*)&Ap[k][tr + 4];
            *(float4*)(rac)     = *(float4*)&Ac[k][tr];
            *(float4*)(rac + 4) = *(float4*)&Ac[k][tr + 4];
            *(float4*)(rb0)     = *(float4*)&B0s[k][tc];
            *(float4*)(rb0 + 4) = *(float4*)&B0s[k][tc + 4];
            *(float4*)(rb1)     = *(float4*)&B1s[k][tc];
            *(float4*)(rb1 + 4) = *(float4*)&B1s[k][tc + 4];
            #pragma unroll
            for (int i = 0; i < 8; i++)
                #pragma unroll
                for (int j = 0; j < 8; j++)
                    acc[i][j] += rap[i] * rb0[j] + rac[i] * rb1[j];
        }
        __syncthreads();
    }

    // epilogue
    float bload[8];
    #pragma unroll
    for (int j = 0; j < 8; j++) bload[j] = bias[n0 + tc + j];
    #pragma unroll
    for (int i = 0; i < 8; i++) {
        int row = m0 + tr + i;
        if (row >= M) continue;
        float* crow = Cout + (size_t)row * N + n0 + tc;
        #pragma unroll
        for (int j = 0; j < 8; j += 4) {
            float4 v;
            v.x = acc[i][j + 0] + bload[j + 0];
            v.y = acc[i][j + 1] + bload[j + 1];
            v.z = acc[i][j + 2] + bload[j + 2];
            v.w = acc[i][j + 3] + bload[j + 3];
            if (ADD_RES) {
                float4 r = *(const float4*)(resid + (size_t)row * N + n0 + tc + j);
                v.x += r.x; v.y += r.y; v.z += r.z; v.w += r.w;
            }
            *(float4*)(crow + j) = v;
        }
    }
}

// ---------------------------------------------------------------------------
__global__ __launch_bounds__(256)
void rmsnorm_kernel(const float* __restrict__ pre,
                    const float* __restrict__ gamma,
                    float* __restrict__ out,
                    int E, float invE)
{
    int t = blockIdx.x;
    const float* row = pre + (size_t)t * E;
    float ss = 0.f;
    for (int i = threadIdx.x * 4; i < E; i += blockDim.x * 4) {
        float4 v = *(const float4*)(row + i);
        ss += v.x * v.x + v.y * v.y + v.z * v.z + v.w * v.w;
    }
    __shared__ float red[32];
    #pragma unroll
    for (int o = 16; o; o >>= 1) ss += __shfl_xor_sync(~0u, ss, o);
    if ((threadIdx.x & 31) == 0) red[threadIdx.x >> 5] = ss;
    __syncthreads();
    if (threadIdx.x < 32) {
        float v = (threadIdx.x < (blockDim.x >> 5)) ? red[threadIdx.x] : 0.f;
        #pragma unroll
        for (int o = 16; o; o >>= 1) v += __shfl_xor_sync(~0u, v, o);
        if (threadIdx.x == 0) red[0] = v;
    }
    __syncthreads();
    float scale = rsqrtf(red[0] * invE + 1e-6f);
    for (int i = threadIdx.x * 4; i < E; i += blockDim.x * 4) {
        float4 v = *(const float4*)(row + i);
        float4 g = *(const float4*)(gamma + i);
        v.x *= scale * g.x; v.y *= scale * g.y;
        v.z *= scale * g.z; v.w *= scale * g.w;
        *(float4*)(out + (size_t)t * E + i) = v;
    }
}

__global__ void lf_copy_kernel(const float* __restrict__ inputs,
                               const int* __restrict__ start,
                               const int* __restrict__ lens,
                               int B, int E, int H, int total,
                               float* __restrict__ out, long long out_size)
{
    int b = blockIdx.x;
    int tlast = start[b] + lens[b] - 1;
    long long base1 = (long long)total * E;
    long long base2 = base1 + (long long)B * E;
    for (int i = threadIdx.x; i < E; i += blockDim.x) {
        long long o = base1 + (long long)b * E + i;
        if (o < out_size) out[o] = inputs[(size_t)tlast * E + i];
    }
    for (int j = threadIdx.x; j < H; j += blockDim.x) {
        long long o = base2 + (long long)b * H + j;
        if (o < out_size) out[o] = g_O1[(size_t)tlast * H + j];
    }
}

// ---------------------------------------------------------------------------
extern "C" void kernel_launch(void* const* d_in, const int* in_sizes, int n_in,
                              void* d_out, int out_size)
{
    const float* inputs = (const float*)d_in[0];
    const float* lf1    = (const float*)d_in[1];
    const float* lf2    = (const float*)d_in[2];
    const float* w1     = (const float*)d_in[3];
    const float* b1     = (const float*)d_in[4];
    const float* w2     = (const float*)d_in[5];
    const float* b2     = (const float*)d_in[6];
    const float* gamma  = (const float*)d_in[7];
    const int*   start  = (const int*)d_in[8];
    const int*   lens   = (const int*)d_in[9];
    const int*   maxlen = (n_in > 10) ? (const int*)d_in[10] : nullptr;

    const int E = in_sizes[7];
    const int H = in_sizes[4];
    const int total = in_sizes[0] / E;
    const int B = in_sizes[9];
    float* out = (float*)d_out;

    if (E > MAX_E || H > MAX_H || total > MAX_TOTAL || B > MAX_B) {
        // unsupported shape — still produce launches so capture isn't empty
        rmsnorm_kernel<<<1, 256>>>((const float*)d_in[0], gamma, out, E, 1.f / E);
        return;
    }

    float *pW1T0, *pW1T1, *pW2T0, *pW2T1, *pO1, *pPre, *pBndX, *pBndO1;
    int* pTok;
    cudaGetSymbolAddress((void**)&pW1T0, g_W1T0);
    cudaGetSymbolAddress((void**)&pW1T1, g_W1T1);
    cudaGetSymbolAddress((void**)&pW2T0, g_W2T0);
    cudaGetSymbolAddress((void**)&pW2T1, g_W2T1);
    cudaGetSymbolAddress((void**)&pO1,   g_O1);
    cudaGetSymbolAddress((void**)&pPre,  g_pre);
    cudaGetSymbolAddress((void**)&pBndX, g_bndX);
    cudaGetSymbolAddress((void**)&pBndO1,g_bndO1);
    cudaGetSymbolAddress((void**)&pTok,  g_tokseq);

    pack_w_kernel<<<256, 256>>>(w1, w2, E, H);
    prep_tok_kernel<<<(total + 255) / 256, 256>>>(start, B, total);
    prep_bnd_kernel<<<B, 256>>>(lf1, lf2, w1, b1, lens, maxlen, E, H);

    // Stage 1: O1 = Xprev@W1_0^T + X@W1_1^T + b1     (M=total, N=H, K=E)
    {
        dim3 grid(H / 128, (total + 127) / 128);
        conv_gemm_kernel<false><<<grid, 256>>>(inputs, pBndX, pW1T0, pW1T1,
                                               b1, nullptr, start,
                                               total, H, E, pO1);
    }
    // Stage 2: pre = O1prev@W2_0^T + O1@W2_1^T + b2 + X   (M=total, N=E, K=H)
    {
        dim3 grid(E / 128, (total + 127) / 128);
        conv_gemm_kernel<true><<<grid, 256>>>(pO1, pBndO1, pW2T0, pW2T1,
                                              b2, inputs, start,
                                              total, E, H, pPre);
    }
    // RMSNorm -> lf_output
    rmsnorm_kernel<<<total, 256>>>(pPre, gamma, out, E, 1.f / (float)E);
    // lf1 / lf2 cache outputs
    lf_copy_kernel<<<B, 256>>>(inputs, start, lens, B, E, H, total,
                               out, (long long)out_size);
}

// round 2
// speedup vs baseline: 3.0668x; 3.0668x over previous
#include <cuda_runtime.h>
#include <cuda_bf16.h>
#include <cstdint>

// ---------------------------------------------------------------------------
// LocalizedFiltering via two shifted-pair GEMMs on bf16 tensor cores with
// 3-term precision split (x ~ xh + xl; x*w ~ xh*wh + xh*wl + xl*wh).
//   O1[t] = W1_0 @ xprev(t) + W1_1 @ x[t] + b1
//   pre[t]= W2_0 @ o1prev(t)+ W2_1 @ O1[t]+ b2 + x[t]
//   out[t]= RMSNorm(pre[t]) * gamma
// Boundary at sequence start p==0:
//   xprev  = (L==max_len) ? lf1_cache[b] : 0
//   o1prev = (L==max_len) ? lf2_cache[b] : b1 (+ W1_0@lf1 iff max_len-L==1)
// Output: [lf_output total*E][lf1 B*E][lf2 B*H]
// ---------------------------------------------------------------------------

#define MAX_TOTAL 24576
#define MAX_E     2048
#define MAX_H     1024
#define MAX_B     64

// packed weights: [variant][ (k/16)*N + n )*16 + k%16 ]
// variants: 0 = W0 hi, 1 = W0 lo, 2 = W1 hi, 3 = W1 lo
__device__ __nv_bfloat16 g_W1p[4][(size_t)MAX_E * MAX_H];
__device__ __nv_bfloat16 g_W2p[4][(size_t)MAX_H * MAX_E];
__device__ float g_O1  [(size_t)MAX_TOTAL * MAX_H];
__device__ float g_pre [(size_t)MAX_TOTAL * MAX_E];
__device__ float g_bndX [MAX_B * MAX_E];
__device__ float g_bndO1[MAX_B * MAX_H];
__device__ int   g_tokseq[MAX_TOTAL];

// ---------------------------------------------------------------------------
__global__ void pack_w_bf16(const float* __restrict__ w1,
                            const float* __restrict__ w2,
                            int E, int H)
{
    int stride = gridDim.x * blockDim.x;
    int idx = blockIdx.x * blockDim.x + threadIdx.x;
    int n1 = H * E;
    // stage 1: w1 (H, E, 2): n in [0,H), k in [0,E)  -> g_W1p, N=H
    for (int i = idx; i < n1; i += stride) {
        int n = i / E, k = i - n * E;
        size_t dst = ((size_t)(k >> 4) * H + n) * 16 + (k & 15);
        float v0 = w1[((size_t)n * E + k) * 2 + 0];
        float v1 = w1[((size_t)n * E + k) * 2 + 1];
        __nv_bfloat16 h0 = __float2bfloat16(v0);
        __nv_bfloat16 h1 = __float2bfloat16(v1);
        g_W1p[0][dst] = h0;
        g_W1p[1][dst] = __float2bfloat16(v0 - __bfloat162float(h0));
        g_W1p[2][dst] = h1;
        g_W1p[3][dst] = __float2bfloat16(v1 - __bfloat162float(h1));
    }
    // stage 2: w2 (E, H, 2): n in [0,E), k in [0,H) -> g_W2p, N=E
    for (int i = idx; i < n1; i += stride) {
        int n = i / H, k = i - n * H;
        size_t dst = ((size_t)(k >> 4) * E + n) * 16 + (k & 15);
        float v0 = w2[((size_t)n * H + k) * 2 + 0];
        float v1 = w2[((size_t)n * H + k) * 2 + 1];
        __nv_bfloat16 h0 = __float2bfloat16(v0);
        __nv_bfloat16 h1 = __float2bfloat16(v1);
        g_W2p[0][dst] = h0;
        g_W2p[1][dst] = __float2bfloat16(v0 - __bfloat162float(h0));
        g_W2p[2][dst] = h1;
        g_W2p[3][dst] = __float2bfloat16(v1 - __bfloat162float(h1));
    }
}

__global__ void prep_tok_kernel(const int* __restrict__ start, int B, int total)
{
    int t = blockIdx.x * blockDim.x + threadIdx.x;
    if (t >= total) return;
    int lo = 0, hi = B - 1;
    while (lo < hi) {
        int mid = (lo + hi + 1) >> 1;
        if (start[mid] <= t) lo = mid; else hi = mid - 1;
    }
    g_tokseq[t] = lo;
}

__global__ void prep_bnd_kernel(const float* __restrict__ lf1,
                                const float* __restrict__ lf2,
                                const float* __restrict__ w1,
                                const float* __restrict__ b1,
                                const int*   __restrict__ lens,
                                const int*   __restrict__ maxlen_ptr,
                                int E, int H)
{
    int b = blockIdx.x;
    int L = lens[b];
    int ml = maxlen_ptr ? maxlen_ptr[0] : 4096;
    bool full = (L == ml);
    for (int i = threadIdx.x; i < E; i += blockDim.x)
        g_bndX[(size_t)b * E + i] = full ? lf1[(size_t)b * E + i] : 0.f;
    int s0 = ml - L;
    for (int n = threadIdx.x; n < H; n += blockDim.x) {
        float v;
        if (full) {
            v = lf2[(size_t)b * H + n];
        } else {
            v = b1[n];
            if (s0 == 1) {
                const float* wr = w1 + (size_t)n * E * 2;
                float acc = 0.f;
                for (int k = 0; k < E; k++) acc += wr[(size_t)k * 2] * lf1[(size_t)b * E + k];
                v += acc;
            }
        }
        g_bndO1[(size_t)b * H + n] = v;
    }
}

// ---------------------------------------------------------------------------
// mma helpers
// ---------------------------------------------------------------------------
__device__ __forceinline__ uint32_t smem_u32(const void* p) {
    return (uint32_t)__cvta_generic_to_shared(p);
}
__device__ __forceinline__ void ldsm_x4(uint32_t* r, uint32_t a) {
    asm volatile("ldmatrix.sync.aligned.m8n8.x4.shared.b16 {%0,%1,%2,%3}, [%4];"
                 : "=r"(r[0]), "=r"(r[1]), "=r"(r[2]), "=r"(r[3]) : "r"(a));
}
__device__ __forceinline__ void ldsm_x2(uint32_t* r, uint32_t a) {
    asm volatile("ldmatrix.sync.aligned.m8n8.x2.shared.b16 {%0,%1}, [%2];"
                 : "=r"(r[0]), "=r"(r[1]) : "r"(a));
}
__device__ __forceinline__ void mma_bf16(float* c, const uint32_t* a, const uint32_t* b) {
    asm volatile("mma.sync.aligned.m16n8k16.row.col.f32.bf16.bf16.f32 "
                 "{%0,%1,%2,%3}, {%4,%5,%6,%7}, {%8,%9}, {%0,%1,%2,%3};"
                 : "+f"(c[0]), "+f"(c[1]), "+f"(c[2]), "+f"(c[3])
                 : "r"(a[0]), "r"(a[1]), "r"(a[2]), "r"(a[3]), "r"(b[0]), "r"(b[1]));
}
__device__ __forceinline__ void cvt4(float4 v, __nv_bfloat16* hp, __nv_bfloat16* lp) {
    __nv_bfloat16 h0 = __float2bfloat16(v.x);
    __nv_bfloat16 h1 = __float2bfloat16(v.y);
    __nv_bfloat16 h2 = __float2bfloat16(v.z);
    __nv_bfloat16 h3 = __float2bfloat16(v.w);
    __nv_bfloat162 hh0; hh0.x = h0; hh0.y = h1;
    __nv_bfloat162 hh1; hh1.x = h2; hh1.y = h3;
    __nv_bfloat162 ll0;
    ll0.x = __float2bfloat16(v.x - __bfloat162float(h0));
    ll0.y = __float2bfloat16(v.y - __bfloat162float(h1));
    __nv_bfloat162 ll1;
    ll1.x = __float2bfloat16(v.z - __bfloat162float(h2));
    ll1.y = __float2bfloat16(v.w - __bfloat162float(h3));
    *(__nv_bfloat162*)(hp)     = hh0;
    *(__nv_bfloat162*)(hp + 2) = hh1;
    *(__nv_bfloat162*)(lp)     = ll0;
    *(__nv_bfloat162*)(lp + 2) = ll1;
}

// ---------------------------------------------------------------------------
// Shifted-pair split-bf16 GEMM. BM=BN=128, BK(f32)=16, 8 warps (64x32 tiles).
// As variants: 0=prev_hi 1=prev_lo 2=cur_hi 3=cur_lo
// Bs variants: 0=W0_hi   1=W0_lo   2=W1_hi  3=W1_lo
// products: A0*B0 + A0*B1 + A1*B0  (prev)  +  A2*B2 + A2*B3 + A3*B2  (cur)
// ---------------------------------------------------------------------------
#define APAD 24
template<bool ADD_RES>
__global__ __launch_bounds__(256, 2)
void conv_mma_kernel(const float* __restrict__ src,
                     const float* __restrict__ bnd,
                     const __nv_bfloat16* __restrict__ Wp, size_t wstride,
                     const float* __restrict__ bias,
                     const float* __restrict__ resid,
                     const int*   __restrict__ start,
                     int M, int N, int K,
                     float* __restrict__ Cout)
{
    __shared__ __nv_bfloat16 As[4][128][APAD];
    __shared__ __nv_bfloat16 Bs[4][128][APAD];

    const int tid  = threadIdx.x;
    const int lane = tid & 31;
    const int wid  = tid >> 5;
    const int m0 = blockIdx.y * 128;
    const int n0 = blockIdx.x * 128;

    // ---- A load assignment: 2 threads/row, each covers float4 quads {aq, aq+2}
    const int arow = tid >> 1;
    const int aq   = (tid & 1) * 4;       // k offset of first float4
    int t = m0 + arow; if (t >= M) t = M - 1;
    const float* aCur;
    const float* aPrev;
    {
        int b = g_tokseq[t];
        aCur  = src + (size_t)t * K;
        aPrev = (t == start[b]) ? (bnd + (size_t)b * K)
                                : (src + (size_t)(t - 1) * K);
    }
    // ---- B load assignment: thread -> (n = tid/2, half = tid&1), 16B each
    const int bn = tid >> 1;
    const int bh = (tid & 1) * 8;

    // ---- mma lane addressing
    const int wm = wid & 1;               // 2 m-warps
    const int wn = wid >> 1;              // 4 n-warps
    const int mbase = wm * 64;
    const int nbase = wn * 32;
    const int a_row_off = ((lane >> 3) & 1) * 8 + (lane & 7);
    const int a_k       = (lane >> 4) * 8;
    const int b_r       = lane & 7;
    const int b_k       = ((lane >> 3) & 1) * 8;

    uint32_t sA[4], sB[4];
    #pragma unroll
    for (int v = 0; v < 4; v++) {
        sA[v] = smem_u32(&As[v][0][0]);
        sB[v] = smem_u32(&Bs[v][0][0]);
    }

    float acc[4][4][4];
    #pragma unroll
    for (int mi = 0; mi < 4; mi++)
        #pragma unroll
        for (int ni = 0; ni < 4; ni++)
            #pragma unroll
            for (int e = 0; e < 4; e++) acc[mi][ni][e] = 0.f;

    const int niter = K >> 4;
    for (int it = 0; it < niter; ++it) {
        // ---- load & convert A
        {
            const float* pc = aCur  + (it << 4) + aq;
            const float* pp = aPrev + (it << 4) + aq;
            float4 c0 = *(const float4*)(pc);
            float4 c1 = *(const float4*)(pc + 8);
            float4 p0 = *(const float4*)(pp);
            float4 p1 = *(const float4*)(pp + 8);
            cvt4(p0, &As[0][arow][aq],     &As[1][arow][aq]);
            cvt4(p1, &As[0][arow][aq + 8], &As[1][arow][aq + 8]);
            cvt4(c0, &As[2][arow][aq],     &As[3][arow][aq]);
            cvt4(c1, &As[2][arow][aq + 8], &As[3][arow][aq + 8]);
        }
        // ---- load B tiles (4 variants, contiguous 4KB each)
        {
            const __nv_bfloat16* wb = Wp + ((size_t)it * N + n0 + bn) * 16 + bh;
            #pragma unroll
            for (int v = 0; v < 4; v++)
                *(uint4*)(&Bs[v][bn][bh]) = *(const uint4*)(wb + v * wstride);
        }
        __syncthreads();

        // ---- 6 products
        uint32_t a[4][4];
        uint32_t b[2];
        #define LOADA(v)                                                        \
            _Pragma("unroll")                                                   \
            for (int mi = 0; mi < 4; mi++)                                      \
                ldsm_x4(a[mi], sA[v] + (uint32_t)(((mbase + mi * 16 + a_row_off) * APAD + a_k) * 2));
        #define PROD(v)                                                         \
            _Pragma("unroll")                                                   \
            for (int ni = 0; ni < 4; ni++) {                                    \
                ldsm_x2(b, sB[v] + (uint32_t)(((nbase + ni * 8 + b_r) * APAD + b_k) * 2)); \
                _Pragma("unroll")                                               \
                for (int mi = 0; mi < 4; mi++) mma_bf16(acc[mi][ni], a[mi], b); \
            }
        LOADA(0) PROD(0) PROD(1)
        LOADA(1) PROD(0)
        LOADA(2) PROD(2) PROD(3)
        LOADA(3) PROD(2)
        #undef LOADA
        #undef PROD
        __syncthreads();
    }

    // ---- epilogue
    const int erow = lane >> 2;
    const int ecol = (lane & 3) * 2;
    #pragma unroll
    for (int mi = 0; mi < 4; mi++) {
        int r0 = m0 + mbase + mi * 16 + erow;
        #pragma unroll
        for (int ni = 0; ni < 4; ni++) {
            int c = n0 + nbase + ni * 8 + ecol;
            float2 bv = *(const float2*)(bias + c);
            float2 o0, o1;
            o0.x = acc[mi][ni][0] + bv.x; o0.y = acc[mi][ni][1] + bv.y;
            o1.x = acc[mi][ni][2] + bv.x; o1.y = acc[mi][ni][3] + bv.y;
            if (ADD_RES) {
                if (r0 < M) {
                    float2 rr = *(const float2*)(resid + (size_t)r0 * N + c);
                    o0.x += rr.x; o0.y += rr.y;
                }
                if (r0 + 8 < M) {
                    float2 rr = *(const float2*)(resid + (size_t)(r0 + 8) * N + c);
                    o1.x += rr.x; o1.y += rr.y;
                }
            }
            if (r0 < M)     *(float2*)(Cout + (size_t)r0 * N + c) = o0;
            if (r0 + 8 < M) *(float2*)(Cout + (size_t)(r0 + 8) * N + c) = o1;
        }
    }
}

// ---------------------------------------------------------------------------
__global__ __launch_bounds__(256)
void rmsnorm_kernel(const float* __restrict__ pre,
                    const float* __restrict__ gamma,
                    float* __restrict__ out,
                    int E, float invE)
{
    int t = blockIdx.x;
    const float* row = pre + (size_t)t * E;
    float ss = 0.f;
    for (int i = threadIdx.x * 4; i < E; i += blockDim.x * 4) {
        float4 v = *(const float4*)(row + i);
        ss += v.x * v.x + v.y * v.y + v.z * v.z + v.w * v.w;
    }
    __shared__ float red[32];
    #pragma unroll
    for (int o = 16; o; o >>= 1) ss += __shfl_xor_sync(~0u, ss, o);
    if ((threadIdx.x & 31) == 0) red[threadIdx.x >> 5] = ss;
    __syncthreads();
    if (threadIdx.x < 32) {
        float v = (threadIdx.x < (blockDim.x >> 5)) ? red[threadIdx.x] : 0.f;
        #pragma unroll
        for (int o = 16; o; o >>= 1) v += __shfl_xor_sync(~0u, v, o);
        if (threadIdx.x == 0) red[0] = v;
    }
    __syncthreads();
    float scale = rsqrtf(red[0] * invE + 1e-6f);
    for (int i = threadIdx.x * 4; i < E; i += blockDim.x * 4) {
        float4 v = *(const float4*)(row + i);
        float4 g = *(const float4*)(gamma + i);
        v.x *= scale * g.x; v.y *= scale * g.y;
        v.z *= scale * g.z; v.w *= scale * g.w;
        *(float4*)(out + (size_t)t * E + i) = v;
    }
}

__global__ void lf_copy_kernel(const float* __restrict__ inputs,
                               const int* __restrict__ start,
                               const int* __restrict__ lens,
                               int B, int E, int H, int total,
                               float* __restrict__ out, long long out_size)
{
    int b = blockIdx.x;
    int tlast = start[b] + lens[b] - 1;
    long long base1 = (long long)total * E;
    long long base2 = base1 + (long long)B * E;
    for (int i = threadIdx.x; i < E; i += blockDim.x) {
        long long o = base1 + (long long)b * E + i;
        if (o < out_size) out[o] = inputs[(size_t)tlast * E + i];
    }
    for (int j = threadIdx.x; j < H; j += blockDim.x) {
        long long o = base2 + (long long)b * H + j;
        if (o < out_size) out[o] = g_O1[(size_t)tlast * H + j];
    }
}

// ---------------------------------------------------------------------------
extern "C" void kernel_launch(void* const* d_in, const int* in_sizes, int n_in,
                              void* d_out, int out_size)
{
    const float* inputs = (const float*)d_in[0];
    const float* lf1    = (const float*)d_in[1];
    const float* lf2    = (const float*)d_in[2];
    const float* w1     = (const float*)d_in[3];
    const float* b1     = (const float*)d_in[4];
    const float* w2     = (const float*)d_in[5];
    const float* b2     = (const float*)d_in[6];
    const float* gamma  = (const float*)d_in[7];
    const int*   start  = (const int*)d_in[8];
    const int*   lens   = (const int*)d_in[9];
    const int*   maxlen = (n_in > 10) ? (const int*)d_in[10] : nullptr;

    const int E = in_sizes[7];
    const int H = in_sizes[4];
    const int total = in_sizes[0] / E;
    const int B = in_sizes[9];
    float* out = (float*)d_out;

    if (E > MAX_E || H > MAX_H || total > MAX_TOTAL || B > MAX_B ||
        (E & 127) || (H & 127)) {
        rmsnorm_kernel<<<1, 256>>>((const float*)d_in[0], gamma, out, E, 1.f / E);
        return;
    }

    float *pO1, *pPre, *pBndX, *pBndO1;
    __nv_bfloat16 *pW1p, *pW2p;
    cudaGetSymbolAddress((void**)&pO1,   g_O1);
    cudaGetSymbolAddress((void**)&pPre,  g_pre);
    cudaGetSymbolAddress((void**)&pBndX, g_bndX);
    cudaGetSymbolAddress((void**)&pBndO1,g_bndO1);
    cudaGetSymbolAddress((void**)&pW1p,  g_W1p);
    cudaGetSymbolAddress((void**)&pW2p,  g_W2p);

    pack_w_bf16<<<256, 256>>>(w1, w2, E, H);
    prep_tok_kernel<<<(total + 255) / 256, 256>>>(start, B, total);
    prep_bnd_kernel<<<B, 256>>>(lf1, lf2, w1, b1, lens, maxlen, E, H);

    const size_t wstride = (size_t)MAX_E * MAX_H; // variant stride in pack arrays

    // Stage 1: O1 = Xprev@W1_0^T + X@W1_1^T + b1   (M=total, N=H, K=E)
    {
        dim3 grid(H / 128, (total + 127) / 128);
        conv_mma_kernel<false><<<grid, 256>>>(inputs, pBndX, pW1p, wstride,
                                              b1, nullptr, start,
                                              total, H, E, pO1);
    }
    // Stage 2: pre = O1prev@W2_0^T + O1@W2_1^T + b2 + X  (M=total, N=E, K=H)
    {
        dim3 grid(E / 128, (total + 127) / 128);
        conv_mma_kernel<true><<<grid, 256>>>(pO1, pBndO1, pW2p, wstride,
                                             b2, inputs, start,
                                             total, E, H, pPre);
    }
    rmsnorm_kernel<<<total, 256>>>(pPre, gamma, out, E, 1.f / (float)E);
    lf_copy_kernel<<<B, 256>>>(inputs, start, lens, B, E, H, total,
                               out, (long long)out_size);
}

// round 4
// speedup vs baseline: 4.3165x; 1.4075x over previous
#include <cuda_runtime.h>
#include <cuda_fp16.h>
#include <cstdint>

// ---------------------------------------------------------------------------
// LocalizedFiltering via shifted-pair GEMMs on mma.sync fp16 tensor cores.
//   O1[t] = W1_0 @ xprev(t) + W1_1 @ x[t] + b1
//   pre[t]= W2_0 @ o1prev(t)+ W2_1 @ O1[t]+ b2 + x[t]
//   out[t]= RMSNorm(pre[t]) * gamma
// Precision: A split to fp16 hi+lo (2-term), W single fp16.
//   4 products/output: prevH*W0 + prevL*W0 + curH*W1 + curL*W1
// Pipeline: cp.async double-buffered, BM=128 BN=256 BK=16, 512 threads.
// Output: [lf_output total*E][lf1 B*E][lf2 B*H]
// ---------------------------------------------------------------------------

#define MAX_TOTAL 24576
#define MAX_E     2048
#define MAX_H     1024
#define MAX_B     64

#define A_TILE   4096          // 128 rows * 32B
#define B_TILE   8192          // 256 rows * 32B
#define B_OFF    16384         // 4 A tiles
#define STAGE    32768
#define DYN_SMEM 65536

// scratch (static __device__; no cudaMalloc allowed)
__device__ __half g_Xh[(size_t)MAX_TOTAL * MAX_E];
__device__ __half g_Xl[(size_t)MAX_TOTAL * MAX_E];
__device__ __half g_O1h[(size_t)MAX_TOTAL * MAX_H];
__device__ __half g_O1l[(size_t)MAX_TOTAL * MAX_H];
__device__ __half g_W1f[(size_t)2 * MAX_H * MAX_E]; // [var][n*E+k]
__device__ __half g_W2f[(size_t)2 * MAX_E * MAX_H]; // [var][n*H+k]
__device__ float  g_pre[(size_t)MAX_TOTAL * MAX_E];
__device__ __half g_bndXh[MAX_B * MAX_E];
__device__ __half g_bndXl[MAX_B * MAX_E];
__device__ __half g_bndOh[MAX_B * MAX_H];
__device__ __half g_bndOl[MAX_B * MAX_H];
__device__ int    g_tokseq[MAX_TOTAL];

// ---------------------------------------------------------------------------
// helpers
// ---------------------------------------------------------------------------
__device__ __forceinline__ uint32_t smem_u32(const void* p) {
    return (uint32_t)__cvta_generic_to_shared(p);
}
__device__ __forceinline__ void cp16(uint32_t dst, const void* src) {
    asm volatile("cp.async.cg.shared.global [%0], [%1], 16;" :: "r"(dst), "l"(src) : "memory");
}
__device__ __forceinline__ void ldsm_x4(uint32_t* r, uint32_t a) {
    asm volatile("ldmatrix.sync.aligned.m8n8.x4.shared.b16 {%0,%1,%2,%3}, [%4];"
                 : "=r"(r[0]), "=r"(r[1]), "=r"(r[2]), "=r"(r[3]) : "r"(a));
}
__device__ __forceinline__ void mma_fp16(float* c, const uint32_t* a, const uint32_t* b) {
    asm volatile("mma.sync.aligned.m16n8k16.row.col.f32.f16.f16.f32 "
                 "{%0,%1,%2,%3}, {%4,%5,%6,%7}, {%8,%9}, {%0,%1,%2,%3};"
                 : "+f"(c[0]), "+f"(c[1]), "+f"(c[2]), "+f"(c[3])
                 : "r"(a[0]), "r"(a[1]), "r"(a[2]), "r"(a[3]), "r"(b[0]), "r"(b[1]));
}
// smem byte offset within a tile for (row, half) with bank-decorrelating XOR
__device__ __forceinline__ uint32_t swz(int row, int half) {
    return (uint32_t)(row * 32 + ((half ^ ((row >> 2) & 1)) << 4));
}

// ---------------------------------------------------------------------------
// prep kernels
// ---------------------------------------------------------------------------
__global__ void split_x_kernel(const float* __restrict__ x, size_t n)
{
    size_t i = ((size_t)blockIdx.x * blockDim.x + threadIdx.x) * 4;
    size_t stride = (size_t)gridDim.x * blockDim.x * 4;
    for (; i < n; i += stride) {
        float4 v = *(const float4*)(x + i);
        __half2 h0 = __floats2half2_rn(v.x, v.y);
        __half2 h1 = __floats2half2_rn(v.z, v.w);
        float2 f0 = __half22float2(h0), f1 = __half22float2(h1);
        __half2 l0 = __floats2half2_rn(v.x - f0.x, v.y - f0.y);
        __half2 l1 = __floats2half2_rn(v.z - f1.x, v.w - f1.y);
        *(__half2*)(g_Xh + i)     = h0;
        *(__half2*)(g_Xh + i + 2) = h1;
        *(__half2*)(g_Xl + i)     = l0;
        *(__half2*)(g_Xl + i + 2) = l1;
    }
}

__global__ void pack_w_kernel(const float* __restrict__ w1,
                              const float* __restrict__ w2, int E, int H)
{
    size_t stride = (size_t)gridDim.x * blockDim.x;
    size_t i0 = (size_t)blockIdx.x * blockDim.x + threadIdx.x;
    size_t n1 = (size_t)H * E;
    for (size_t i = i0; i < n1; i += stride) {
        g_W1f[i]      = __float2half_rn(w1[i * 2]);
        g_W1f[n1 + i] = __float2half_rn(w1[i * 2 + 1]);
    }
    size_t n2 = (size_t)E * H;
    for (size_t i = i0; i < n2; i += stride) {
        g_W2f[i]      = __float2half_rn(w2[i * 2]);
        g_W2f[n2 + i] = __float2half_rn(w2[i * 2 + 1]);
    }
}

__global__ void prep_tok_kernel(const int* __restrict__ start, int B, int total)
{
    int t = blockIdx.x * blockDim.x + threadIdx.x;
    if (t >= total) return;
    int lo = 0, hi = B - 1;
    while (lo < hi) {
        int mid = (lo + hi + 1) >> 1;
        if (start[mid] <= t) lo = mid; else hi = mid - 1;
    }
    g_tokseq[t] = lo;
}

__global__ void prep_bnd_kernel(const float* __restrict__ lf1,
                                const float* __restrict__ lf2,
                                const float* __restrict__ w1,
                                const float* __restrict__ b1,
                                const int*   __restrict__ lens,
                                const int*   __restrict__ maxlen_ptr,
                                int E, int H)
{
    int b = blockIdx.x;
    int L = lens[b];
    int ml = maxlen_ptr ? maxlen_ptr[0] : 4096;
    bool full = (L == ml);
    for (int i = threadIdx.x; i < E; i += blockDim.x) {
        float v = full ? lf1[(size_t)b * E + i] : 0.f;
        __half h = __float2half_rn(v);
        g_bndXh[(size_t)b * E + i] = h;
        g_bndXl[(size_t)b * E + i] = __float2half_rn(v - __half2float(h));
    }
    int s0 = ml - L;
    for (int n = threadIdx.x; n < H; n += blockDim.x) {
        float v;
        if (full) {
            v = lf2[(size_t)b * H + n];
        } else {
            v = b1[n];
            if (s0 == 1) {
                const float* wr = w1 + (size_t)n * E * 2;
                float acc = 0.f;
                for (int k = 0; k < E; k++) acc += wr[(size_t)k * 2] * lf1[(size_t)b * E + k];
                v += acc;
            }
        }
        __half h = __float2half_rn(v);
        g_bndOh[(size_t)b * H + n] = h;
        g_bndOl[(size_t)b * H + n] = __float2half_rn(v - __half2float(h));
    }
}

// ---------------------------------------------------------------------------
// Shifted-pair fp16 GEMM. BM=128 BN=256 BK=16, 512 threads (16 warps, 64x32).
// A variants in smem: 0=prevH 1=prevL 2=curH 3=curL; B variants: 0=W0 1=W1.
// ---------------------------------------------------------------------------
template<bool STAGE2>
__global__ __launch_bounds__(512, 1)
void conv_tc(const __half* __restrict__ srcH, const __half* __restrict__ srcL,
             const __half* __restrict__ bndH, const __half* __restrict__ bndL,
             const __half* __restrict__ Wf, size_t wvar,
             const float* __restrict__ bias,
             const float* __restrict__ resid,
             const int* __restrict__ start,
             int M, int Nfull, int K,
             float* __restrict__ outF,
             __half* __restrict__ outH, __half* __restrict__ outL)
{
    extern __shared__ char sm[];
    const uint32_t sbase = smem_u32(sm);
    const int tid = threadIdx.x;
    const int lane = tid & 31;
    const int wid = tid >> 5;
    const int m0 = blockIdx.y * 128;
    const int n0 = blockIdx.x * 256;

    // ---- cp.async slot setup: 2 A slots + 2 B slots per thread ----------
    const __half* asrc[2]; uint32_t adst[2];
    #pragma unroll
    for (int i = 0; i < 2; i++) {
        int s = tid + i * 512;
        int var = s >> 8;            // 0=prevH 1=prevL 2=curH 3=curL
        int rem = s & 255;
        int row = rem >> 1;
        int half = rem & 1;
        int t = m0 + row; if (t >= M) t = M - 1;
        const __half* arr;
        bool lo = (var & 1);
        if (var < 2) {
            int b = g_tokseq[t];
            if (t == start[b]) arr = (lo ? bndL : bndH) + (size_t)b * K;
            else               arr = (lo ? srcL : srcH) + (size_t)(t - 1) * K;
        } else {
            arr = (lo ? srcL : srcH) + (size_t)t * K;
        }
        asrc[i] = arr + half * 8;
        adst[i] = (uint32_t)(var * A_TILE) + swz(row, half);
    }
    const __half* bsrc[2]; uint32_t bdst[2];
    #pragma unroll
    for (int i = 0; i < 2; i++) {
        int s = tid + i * 512;
        int var = s >> 9;
        int rem = s & 511;
        int n = rem >> 1;
        int half = rem & 1;
        bsrc[i] = Wf + (size_t)var * wvar + (size_t)(n0 + n) * K + half * 8;
        bdst[i] = (uint32_t)(B_OFF + var * B_TILE) + swz(n, half);
    }

    // ---- mma lane constants ----------------------------------------------
    const int wm = wid & 1;
    const int wn = wid >> 1;
    const int mbase = wm * 64;
    const int nbase = wn * 32;
    const int a_row_off = ((lane >> 3) & 1) * 8 + (lane & 7);
    const int a_kh = lane >> 4;                 // 0..1 (k half)
    const int b_row_off = ((lane >> 4) & 1) * 8 + (lane & 7);
    const int b_h = (lane >> 3) & 1;

    float acc[4][4][4];
    #pragma unroll
    for (int mi = 0; mi < 4; mi++)
        #pragma unroll
        for (int ni = 0; ni < 4; ni++)
            #pragma unroll
            for (int e = 0; e < 4; e++) acc[mi][ni][e] = 0.f;

    auto issue = [&](int it, int stg) {
        uint32_t sb = sbase + stg * STAGE;
        cp16(sb + adst[0], asrc[0] + it * 16);
        cp16(sb + adst[1], asrc[1] + it * 16);
        cp16(sb + bdst[0], bsrc[0] + it * 16);
        cp16(sb + bdst[1], bsrc[1] + it * 16);
        asm volatile("cp.async.commit_group;" ::: "memory");
    };

    const int niter = K >> 4;
    issue(0, 0);

    for (int it = 0; it < niter; ++it) {
        const int cur = it & 1;
        asm volatile("cp.async.wait_group 0;" ::: "memory");
        __syncthreads();
        if (it + 1 < niter) issue(it + 1, cur ^ 1);

        const uint32_t base = sbase + cur * STAGE;
        // B fragments: 2 variants x (2 ldsm_x4 covering 32 n)
        uint32_t bb[2][8];
        #pragma unroll
        for (int v = 0; v < 2; v++)
            #pragma unroll
            for (int g = 0; g < 2; g++) {
                int row = nbase + g * 16 + b_row_off;
                ldsm_x4(&bb[v][g * 4], base + B_OFF + v * B_TILE + swz(row, b_h));
            }
        // A variants: pH,pL -> W0 ; cH,cL -> W1
        #pragma unroll
        for (int av = 0; av < 4; av++) {
            uint32_t a[4][4];
            #pragma unroll
            for (int mi = 0; mi < 4; mi++) {
                int r = mbase + mi * 16 + a_row_off;
                ldsm_x4(a[mi], base + av * A_TILE + swz(r, a_kh));
            }
            const int v = av >> 1;
            #pragma unroll
            for (int ni = 0; ni < 4; ni++)
                #pragma unroll
                for (int mi = 0; mi < 4; mi++)
                    mma_fp16(acc[mi][ni], a[mi], &bb[v][ni * 2]);
        }
        __syncthreads();
    }

    // ---- epilogue ----------------------------------------------------------
    const int erow = lane >> 2;
    const int ecol = (lane & 3) * 2;
    #pragma unroll
    for (int mi = 0; mi < 4; mi++) {
        int r0 = m0 + mbase + mi * 16 + erow;
        int r1 = r0 + 8;
        #pragma unroll
        for (int ni = 0; ni < 4; ni++) {
            int c = n0 + nbase + ni * 8 + ecol;
            float bx = bias[c], by = bias[c + 1];
            float v00 = acc[mi][ni][0] + bx, v01 = acc[mi][ni][1] + by;
            float v10 = acc[mi][ni][2] + bx, v11 = acc[mi][ni][3] + by;
            if (STAGE2) {
                if (r0 < M) {
                    float2 rr = *(const float2*)(resid + (size_t)r0 * Nfull + c);
                    float2 o = make_float2(v00 + rr.x, v01 + rr.y);
                    *(float2*)(outF + (size_t)r0 * Nfull + c) = o;
                }
                if (r1 < M) {
                    float2 rr = *(const float2*)(resid + (size_t)r1 * Nfull + c);
                    float2 o = make_float2(v10 + rr.x, v11 + rr.y);
                    *(float2*)(outF + (size_t)r1 * Nfull + c) = o;
                }
            } else {
                if (r0 < M) {
                    __half2 h = __floats2half2_rn(v00, v01);
                    float2 hf = __half22float2(h);
                    __half2 l = __floats2half2_rn(v00 - hf.x, v01 - hf.y);
                    *(__half2*)(outH + (size_t)r0 * Nfull + c) = h;
                    *(__half2*)(outL + (size_t)r0 * Nfull + c) = l;
                }
                if (r1 < M) {
                    __half2 h = __floats2half2_rn(v10, v11);
                    float2 hf = __half22float2(h);
                    __half2 l = __floats2half2_rn(v10 - hf.x, v11 - hf.y);
                    *(__half2*)(outH + (size_t)r1 * Nfull + c) = h;
                    *(__half2*)(outL + (size_t)r1 * Nfull + c) = l;
                }
            }
        }
    }
}

// ---------------------------------------------------------------------------
__global__ __launch_bounds__(256)
void rmsnorm_kernel(const float* __restrict__ pre,
                    const float* __restrict__ gamma,
                    float* __restrict__ out, int E, float invE)
{
    int t = blockIdx.x;
    const float* row = pre + (size_t)t * E;
    float ss = 0.f;
    for (int i = threadIdx.x * 4; i < E; i += blockDim.x * 4) {
        float4 v = *(const float4*)(row + i);
        ss += v.x * v.x + v.y * v.y + v.z * v.z + v.w * v.w;
    }
    __shared__ float red[32];
    #pragma unroll
    for (int o = 16; o; o >>= 1) ss += __shfl_xor_sync(~0u, ss, o);
    if ((threadIdx.x & 31) == 0) red[threadIdx.x >> 5] = ss;
    __syncthreads();
    if (threadIdx.x < 32) {
        float v = (threadIdx.x < (blockDim.x >> 5)) ? red[threadIdx.x] : 0.f;
        #pragma unroll
        for (int o = 16; o; o >>= 1) v += __shfl_xor_sync(~0u, v, o);
        if (threadIdx.x == 0) red[0] = v;
    }
    __syncthreads();
    float scale = rsqrtf(red[0] * invE + 1e-6f);
    for (int i = threadIdx.x * 4; i < E; i += blockDim.x * 4) {
        float4 v = *(const float4*)(row + i);
        float4 g = *(const float4*)(gamma + i);
        v.x *= scale * g.x; v.y *= scale * g.y;
        v.z *= scale * g.z; v.w *= scale * g.w;
        *(float4*)(out + (size_t)t * E + i) = v;
    }
}

__global__ void lf_kernel(const float* __restrict__ inputs,
                          const int* __restrict__ start,
                          const int* __restrict__ lens,
                          int B, int E, int H, int total,
                          float* __restrict__ out, long long out_size)
{
    int b = blockIdx.x;
    int last = start[b] + lens[b] - 1;
    long long base1 = (long long)total * E;
    long long base2 = base1 + (long long)B * E;
    for (int i = threadIdx.x; i < E; i += blockDim.x) {
        long long o = base1 + (long long)b * E + i;
        if (o < out_size) out[o] = inputs[(size_t)last * E + i];
    }
    for (int n = threadIdx.x; n < H; n += blockDim.x) {
        float v = __half2float(g_O1h[(size_t)last * H + n])
                + __half2float(g_O1l[(size_t)last * H + n]);
        long long o = base2 + (long long)b * H + n;
        if (o < out_size) out[o] = v;
    }
}

__global__ void fallback_kernel(float* out, int n) {
    int i = blockIdx.x * blockDim.x + threadIdx.x;
    if (i < n) out[i] = 0.f;
}

// ---------------------------------------------------------------------------
extern "C" void kernel_launch(void* const* d_in, const int* in_sizes, int n_in,
                              void* d_out, int out_size)
{
    const float* inputs = (const float*)d_in[0];
    const float* lf1    = (const float*)d_in[1];
    const float* lf2    = (const float*)d_in[2];
    const float* w1     = (const float*)d_in[3];
    const float* b1     = (const float*)d_in[4];
    const float* w2     = (const float*)d_in[5];
    const float* b2     = (const float*)d_in[6];
    const float* gamma  = (const float*)d_in[7];
    const int*   start  = (const int*)d_in[8];
    const int*   lens   = (const int*)d_in[9];
    const int*   maxlen = (n_in > 10) ? (const int*)d_in[10] : nullptr;

    const int E = in_sizes[7];
    const int H = in_sizes[4];
    const int total = in_sizes[0] / E;
    const int B = in_sizes[9];
    float* out = (float*)d_out;

    if (E > MAX_E || H > MAX_H || total > MAX_TOTAL || B > MAX_B ||
        (E & 255) || (H & 255) || (E & 15) || (H & 15)) {
        fallback_kernel<<<(out_size + 255) / 256, 256>>>(out, out_size);
        return;
    }

    __half *pXh, *pXl, *pO1h, *pO1l, *pW1f, *pW2f, *pBXh, *pBXl, *pBOh, *pBOl;
    float *pPre;
    cudaGetSymbolAddress((void**)&pXh,  g_Xh);
    cudaGetSymbolAddress((void**)&pXl,  g_Xl);
    cudaGetSymbolAddress((void**)&pO1h, g_O1h);
    cudaGetSymbolAddress((void**)&pO1l, g_O1l);
    cudaGetSymbolAddress((void**)&pW1f, g_W1f);
    cudaGetSymbolAddress((void**)&pW2f, g_W2f);
    cudaGetSymbolAddress((void**)&pBXh, g_bndXh);
    cudaGetSymbolAddress((void**)&pBXl, g_bndXl);
    cudaGetSymbolAddress((void**)&pBOh, g_bndOh);
    cudaGetSymbolAddress((void**)&pBOl, g_bndOl);
    cudaGetSymbolAddress((void**)&pPre, g_pre);

    cudaFuncSetAttribute(conv_tc<false>, cudaFuncAttributeMaxDynamicSharedMemorySize, DYN_SMEM);
    cudaFuncSetAttribute(conv_tc<true>,  cudaFuncAttributeMaxDynamicSharedMemorySize, DYN_SMEM);

    split_x_kernel<<<512, 256>>>(inputs, (size_t)total * E);
    pack_w_kernel<<<512, 256>>>(w1, w2, E, H);
    prep_tok_kernel<<<(total + 255) / 256, 256>>>(start, B, total);
    prep_bnd_kernel<<<B, 256>>>(lf1, lf2, w1, b1, lens, maxlen, E, H);

    // Stage 1: O1(h/l) = Xprev@W1_0 + X@W1_1 + b1   (M=total, N=H, K=E)
    {
        dim3 grid(H / 256, (total + 127) / 128);
        conv_tc<false><<<grid, 512, DYN_SMEM>>>(pXh, pXl, pBXh, pBXl,
                                                pW1f, (size_t)H * E,
                                                b1, nullptr, start,
                                                total, H, E,
                                                nullptr, pO1h, pO1l);
    }
    // Stage 2: pre = O1prev@W2_0 + O1@W2_1 + b2 + x (M=total, N=E, K=H)
    {
        dim3 grid(E / 256, (total + 127) / 128);
        conv_tc<true><<<grid, 512, DYN_SMEM>>>(pO1h, pO1l, pBOh, pBOl,
                                               pW2f, (size_t)E * H,
                                               b2, inputs, start,
                                               total, E, H,
                                               pPre, nullptr, nullptr);
    }
    rmsnorm_kernel<<<total, 256>>>(pPre, gamma, out, E, 1.f / (float)E);
    lf_kernel<<<B, 256>>>(inputs, start, lens, B, E, H, total,
                          out, (long long)out_size);
}

// round 5
// speedup vs baseline: 6.6799x; 1.5475x over previous
#include <cuda_runtime.h>
#include <cuda_fp16.h>
#include <cstdint>

// ---------------------------------------------------------------------------
// LocalizedFiltering via shifted-pair GEMMs on mma.sync fp16 tensor cores.
//   O1[t] = W1_0 @ xprev(t) + W1_1 @ x[t] + b1
//   pre[t]= W2_0 @ o1prev(t)+ W2_1 @ O1[t]+ b2 + x[t]
//   out[t]= RMSNorm(pre[t]) * gamma
// Precision: single fp16 A and W, fp32 accumulate (2 products per output).
// Pipeline: 4-stage cp.async ring (wait_group 2), BM=128 BN=256 BK=16,
// 512 threads, 1 sync per K-step.
// Output: [lf_output total*E][lf1 B*E][lf2 B*H]
// ---------------------------------------------------------------------------

#define MAX_TOTAL 24576
#define MAX_E     2048
#define MAX_H     1024
#define MAX_B     64

#define A_TILE   4096          // 128 rows * 32B
#define B_TILE   8192          // 256 rows * 32B
#define B_OFF    8192          // 2 A tiles
#define STAGE    24576
#define NSTAGE   4
#define DYN_SMEM (STAGE * NSTAGE)

// scratch (static __device__; no cudaMalloc allowed)
__device__ __half g_Xh [(size_t)MAX_TOTAL * MAX_E];
__device__ __half g_O1h[(size_t)MAX_TOTAL * MAX_H];
__device__ __half g_W1f[(size_t)2 * MAX_H * MAX_E]; // [var][n*E+k]
__device__ __half g_W2f[(size_t)2 * MAX_E * MAX_H]; // [var][n*H+k]
__device__ float  g_pre[(size_t)MAX_TOTAL * MAX_E];
__device__ __half g_bndXh[MAX_B * MAX_E];
__device__ __half g_bndOh[MAX_B * MAX_H];
__device__ int    g_tokseq[MAX_TOTAL];

// ---------------------------------------------------------------------------
// helpers
// ---------------------------------------------------------------------------
__device__ __forceinline__ uint32_t smem_u32(const void* p) {
    return (uint32_t)__cvta_generic_to_shared(p);
}
__device__ __forceinline__ void cp16(uint32_t dst, const void* src) {
    asm volatile("cp.async.cg.shared.global [%0], [%1], 16;" :: "r"(dst), "l"(src) : "memory");
}
__device__ __forceinline__ void cp_commit() {
    asm volatile("cp.async.commit_group;" ::: "memory");
}
__device__ __forceinline__ void cp_wait2() {
    asm volatile("cp.async.wait_group 2;" ::: "memory");
}
__device__ __forceinline__ void ldsm_x4(uint32_t* r, uint32_t a) {
    asm volatile("ldmatrix.sync.aligned.m8n8.x4.shared.b16 {%0,%1,%2,%3}, [%4];"
                 : "=r"(r[0]), "=r"(r[1]), "=r"(r[2]), "=r"(r[3]) : "r"(a));
}
__device__ __forceinline__ void mma_fp16(float* c, const uint32_t* a, const uint32_t* b) {
    asm volatile("mma.sync.aligned.m16n8k16.row.col.f32.f16.f16.f32 "
                 "{%0,%1,%2,%3}, {%4,%5,%6,%7}, {%8,%9}, {%0,%1,%2,%3};"
                 : "+f"(c[0]), "+f"(c[1]), "+f"(c[2]), "+f"(c[3])
                 : "r"(a[0]), "r"(a[1]), "r"(a[2]), "r"(a[3]), "r"(b[0]), "r"(b[1]));
}
// smem byte offset within a tile for (row, half16B) with bank-decorrelating XOR
__device__ __forceinline__ uint32_t swz(int row, int half) {
    return (uint32_t)(row * 32 + ((half ^ ((row >> 2) & 1)) << 4));
}

// ---------------------------------------------------------------------------
// prep kernels
// ---------------------------------------------------------------------------
__global__ void split_x_kernel(const float* __restrict__ x, size_t n)
{
    size_t i = ((size_t)blockIdx.x * blockDim.x + threadIdx.x) * 4;
    size_t stride = (size_t)gridDim.x * blockDim.x * 4;
    for (; i < n; i += stride) {
        float4 v = *(const float4*)(x + i);
        *(__half2*)(g_Xh + i)     = __floats2half2_rn(v.x, v.y);
        *(__half2*)(g_Xh + i + 2) = __floats2half2_rn(v.z, v.w);
    }
}

__global__ void pack_w_kernel(const float* __restrict__ w1,
                              const float* __restrict__ w2, int E, int H)
{
    size_t stride = (size_t)gridDim.x * blockDim.x;
    size_t i0 = (size_t)blockIdx.x * blockDim.x + threadIdx.x;
    size_t n1 = (size_t)H * E;
    for (size_t i = i0; i < n1; i += stride) {
        g_W1f[i]      = __float2half_rn(w1[i * 2]);
        g_W1f[n1 + i] = __float2half_rn(w1[i * 2 + 1]);
    }
    size_t n2 = (size_t)E * H;
    for (size_t i = i0; i < n2; i += stride) {
        g_W2f[i]      = __float2half_rn(w2[i * 2]);
        g_W2f[n2 + i] = __float2half_rn(w2[i * 2 + 1]);
    }
}

__global__ void prep_tok_kernel(const int* __restrict__ start, int B, int total)
{
    int t = blockIdx.x * blockDim.x + threadIdx.x;
    if (t >= total) return;
    int lo = 0, hi = B - 1;
    while (lo < hi) {
        int mid = (lo + hi + 1) >> 1;
        if (start[mid] <= t) lo = mid; else hi = mid - 1;
    }
    g_tokseq[t] = lo;
}

__global__ void prep_bnd_kernel(const float* __restrict__ lf1,
                                const float* __restrict__ lf2,
                                const float* __restrict__ w1,
                                const float* __restrict__ b1,
                                const int*   __restrict__ lens,
                                const int*   __restrict__ maxlen_ptr,
                                int E, int H)
{
    int b = blockIdx.x;
    int L = lens[b];
    int ml = maxlen_ptr ? maxlen_ptr[0] : 4096;
    bool full = (L == ml);
    for (int i = threadIdx.x; i < E; i += blockDim.x) {
        float v = full ? lf1[(size_t)b * E + i] : 0.f;
        g_bndXh[(size_t)b * E + i] = __float2half_rn(v);
    }
    int s0 = ml - L;
    for (int n = threadIdx.x; n < H; n += blockDim.x) {
        float v;
        if (full) {
            v = lf2[(size_t)b * H + n];
        } else {
            v = b1[n];
            if (s0 == 1) {
                const float* wr = w1 + (size_t)n * E * 2;
                float acc = 0.f;
                for (int k = 0; k < E; k++) acc += wr[(size_t)k * 2] * lf1[(size_t)b * E + k];
                v += acc;
            }
        }
        g_bndOh[(size_t)b * H + n] = __float2half_rn(v);
    }
}

// ---------------------------------------------------------------------------
// Shifted-pair fp16 GEMM. BM=128 BN=256 BK=16, 512 threads (16 warps, 64x32).
// A variants in smem: 0=prev 1=cur; B variants: 0=W0 1=W1.
// ---------------------------------------------------------------------------
template<bool STAGE2>
__global__ __launch_bounds__(512, 1)
void conv_tc(const __half* __restrict__ srcH,
             const __half* __restrict__ bndH,
             const __half* __restrict__ Wf, size_t wvar,
             const float* __restrict__ bias,
             const float* __restrict__ resid,
             const int* __restrict__ start,
             int M, int Nfull, int K,
             float* __restrict__ outF,
             __half* __restrict__ outH)
{
    extern __shared__ char sm[];
    const uint32_t sbase = smem_u32(sm);
    const int tid = threadIdx.x;
    const int lane = tid & 31;
    const int wid = tid >> 5;
    const int m0 = blockIdx.y * 128;
    const int n0 = blockIdx.x * 256;

    // ---- cp.async slots: 1 A slot + 2 B slots per thread ------------------
    const __half* asrc; uint32_t adst;
    {
        int var = tid >> 8;          // 0=prev 1=cur
        int rem = tid & 255;
        int row = rem >> 1;
        int half = rem & 1;
        int t = m0 + row; if (t >= M) t = M - 1;
        const __half* arr;
        if (var == 0) {
            int b = g_tokseq[t];
            arr = (t == start[b]) ? (bndH + (size_t)b * K)
                                  : (srcH + (size_t)(t - 1) * K);
        } else {
            arr = srcH + (size_t)t * K;
        }
        asrc = arr + half * 8;
        adst = (uint32_t)(var * A_TILE) + swz(row, half);
    }
    const __half* bsrc[2]; uint32_t bdst[2];
    #pragma unroll
    for (int i = 0; i < 2; i++) {
        int s = tid + i * 512;
        int var = s >> 9;
        int rem = s & 511;
        int n = rem >> 1;
        int half = rem & 1;
        bsrc[i] = Wf + (size_t)var * wvar + (size_t)(n0 + n) * K + half * 8;
        bdst[i] = (uint32_t)(B_OFF + var * B_TILE) + swz(n, half);
    }

    // ---- mma lane constants ------------------------------------------------
    const int wm = wid & 1;
    const int wn = wid >> 1;
    const int mbase = wm * 64;
    const int nbase = wn * 32;
    const int a_row_off = ((lane >> 3) & 1) * 8 + (lane & 7);
    const int a_kh = lane >> 4;
    const int b_row_off = ((lane >> 4) & 1) * 8 + (lane & 7);
    const int b_h = (lane >> 3) & 1;

    float acc[4][4][4];
    #pragma unroll
    for (int mi = 0; mi < 4; mi++)
        #pragma unroll
        for (int ni = 0; ni < 4; ni++)
            #pragma unroll
            for (int e = 0; e < 4; e++) acc[mi][ni][e] = 0.f;

    auto issue = [&](int it) {
        uint32_t sb = sbase + (it & (NSTAGE - 1)) * STAGE;
        cp16(sb + adst, asrc + it * 16);
        cp16(sb + bdst[0], bsrc[0] + it * 16);
        cp16(sb + bdst[1], bsrc[1] + it * 16);
        cp_commit();
    };

    const int niter = K >> 4;
    // prologue: 3 groups in flight
    issue(0); issue(1); issue(2);

    for (int it = 0; it < niter; ++it) {
        cp_wait2();               // groups <= it complete
        __syncthreads();          // all warps done with slot (it-1) too
        if (it + 3 < niter) issue(it + 3);
        else cp_commit();         // empty group keeps count uniform

        const uint32_t base = sbase + (it & (NSTAGE - 1)) * STAGE;
        uint32_t bb[2][8];
        #pragma unroll
        for (int v = 0; v < 2; v++)
            #pragma unroll
            for (int g = 0; g < 2; g++) {
                int row = nbase + g * 16 + b_row_off;
                ldsm_x4(&bb[v][g * 4], base + B_OFF + v * B_TILE + swz(row, b_h));
            }
        #pragma unroll
        for (int av = 0; av < 2; av++) {
            uint32_t a[4][4];
            #pragma unroll
            for (int mi = 0; mi < 4; mi++) {
                int r = mbase + mi * 16 + a_row_off;
                ldsm_x4(a[mi], base + av * A_TILE + swz(r, a_kh));
            }
            #pragma unroll
            for (int ni = 0; ni < 4; ni++)
                #pragma unroll
                for (int mi = 0; mi < 4; mi++)
                    mma_fp16(acc[mi][ni], a[mi], &bb[av][ni * 2]);
        }
    }

    // ---- epilogue ----------------------------------------------------------
    const int erow = lane >> 2;
    const int ecol = (lane & 3) * 2;
    #pragma unroll
    for (int mi = 0; mi < 4; mi++) {
        int r0 = m0 + mbase + mi * 16 + erow;
        int r1 = r0 + 8;
        #pragma unroll
        for (int ni = 0; ni < 4; ni++) {
            int c = n0 + nbase + ni * 8 + ecol;
            float bx = bias[c], by = bias[c + 1];
            float v00 = acc[mi][ni][0] + bx, v01 = acc[mi][ni][1] + by;
            float v10 = acc[mi][ni][2] + bx, v11 = acc[mi][ni][3] + by;
            if (STAGE2) {
                if (r0 < M) {
                    float2 rr = *(const float2*)(resid + (size_t)r0 * Nfull + c);
                    *(float2*)(outF + (size_t)r0 * Nfull + c) =
                        make_float2(v00 + rr.x, v01 + rr.y);
                }
                if (r1 < M) {
                    float2 rr = *(const float2*)(resid + (size_t)r1 * Nfull + c);
                    *(float2*)(outF + (size_t)r1 * Nfull + c) =
                        make_float2(v10 + rr.x, v11 + rr.y);
                }
            } else {
                if (r0 < M)
                    *(__half2*)(outH + (size_t)r0 * Nfull + c) = __floats2half2_rn(v00, v01);
                if (r1 < M)
                    *(__half2*)(outH + (size_t)r1 * Nfull + c) = __floats2half2_rn(v10, v11);
            }
        }
    }
}

// ---------------------------------------------------------------------------
__global__ __launch_bounds__(256)
void rmsnorm_kernel(const float* __restrict__ pre,
                    const float* __restrict__ gamma,
                    float* __restrict__ out, int E, float invE)
{
    int t = blockIdx.x;
    const float* row = pre + (size_t)t * E;
    float ss = 0.f;
    for (int i = threadIdx.x * 4; i < E; i += blockDim.x * 4) {
        float4 v = *(const float4*)(row + i);
        ss += v.x * v.x + v.y * v.y + v.z * v.z + v.w * v.w;
    }
    __shared__ float red[32];
    #pragma unroll
    for (int o = 16; o; o >>= 1) ss += __shfl_xor_sync(~0u, ss, o);
    if ((threadIdx.x & 31) == 0) red[threadIdx.x >> 5] = ss;
    __syncthreads();
    if (threadIdx.x < 32) {
        float v = (threadIdx.x < (blockDim.x >> 5)) ? red[threadIdx.x] : 0.f;
        #pragma unroll
        for (int o = 16; o; o >>= 1) v += __shfl_xor_sync(~0u, v, o);
        if (threadIdx.x == 0) red[0] = v;
    }
    __syncthreads();
    float scale = rsqrtf(red[0] * invE + 1e-6f);
    for (int i = threadIdx.x * 4; i < E; i += blockDim.x * 4) {
        float4 v = *(const float4*)(row + i);
        float4 g = *(const float4*)(gamma + i);
        v.x *= scale * g.x; v.y *= scale * g.y;
        v.z *= scale * g.z; v.w *= scale * g.w;
        *(float4*)(out + (size_t)t * E + i) = v;
    }
}

__global__ void lf_kernel(const float* __restrict__ inputs,
                          const int* __restrict__ start,
                          const int* __restrict__ lens,
                          int B, int E, int H, int total,
                          float* __restrict__ out, long long out_size)
{
    int b = blockIdx.x;
    int last = start[b] + lens[b] - 1;
    long long base1 = (long long)total * E;
    long long base2 = base1 + (long long)B * E;
    for (int i = threadIdx.x; i < E; i += blockDim.x) {
        long long o = base1 + (long long)b * E + i;
        if (o < out_size) out[o] = inputs[(size_t)last * E + i];
    }
    for (int n = threadIdx.x; n < H; n += blockDim.x) {
        long long o = base2 + (long long)b * H + n;
        if (o < out_size) out[o] = __half2float(g_O1h[(size_t)last * H + n]);
    }
}

__global__ void fallback_kernel(float* out, int n) {
    int i = blockIdx.x * blockDim.x + threadIdx.x;
    if (i < n) out[i] = 0.f;
}

// ---------------------------------------------------------------------------
extern "C" void kernel_launch(void* const* d_in, const int* in_sizes, int n_in,
                              void* d_out, int out_size)
{
    const float* inputs = (const float*)d_in[0];
    const float* lf1    = (const float*)d_in[1];
    const float* lf2    = (const float*)d_in[2];
    const float* w1     = (const float*)d_in[3];
    const float* b1     = (const float*)d_in[4];
    const float* w2     = (const float*)d_in[5];
    const float* b2     = (const float*)d_in[6];
    const float* gamma  = (const float*)d_in[7];
    const int*   start  = (const int*)d_in[8];
    const int*   lens   = (const int*)d_in[9];
    const int*   maxlen = (n_in > 10) ? (const int*)d_in[10] : nullptr;

    const int E = in_sizes[7];
    const int H = in_sizes[4];
    const int total = in_sizes[0] / E;
    const int B = in_sizes[9];
    float* out = (float*)d_out;

    if (E > MAX_E || H > MAX_H || total > MAX_TOTAL || B > MAX_B ||
        (E & 255) || (H & 255)) {
        fallback_kernel<<<(out_size + 255) / 256, 256>>>(out, out_size);
        return;
    }

    __half *pXh, *pO1h, *pW1f, *pW2f, *pBXh, *pBOh;
    float *pPre;
    cudaGetSymbolAddress((void**)&pXh,  g_Xh);
    cudaGetSymbolAddress((void**)&pO1h, g_O1h);
    cudaGetSymbolAddress((void**)&pW1f, g_W1f);
    cudaGetSymbolAddress((void**)&pW2f, g_W2f);
    cudaGetSymbolAddress((void**)&pBXh, g_bndXh);
    cudaGetSymbolAddress((void**)&pBOh, g_bndOh);
    cudaGetSymbolAddress((void**)&pPre, g_pre);

    cudaFuncSetAttribute(conv_tc<false>, cudaFuncAttributeMaxDynamicSharedMemorySize, DYN_SMEM);
    cudaFuncSetAttribute(conv_tc<true>,  cudaFuncAttributeMaxDynamicSharedMemorySize, DYN_SMEM);

    split_x_kernel<<<512, 256>>>(inputs, (size_t)total * E);
    pack_w_kernel<<<512, 256>>>(w1, w2, E, H);
    prep_tok_kernel<<<(total + 255) / 256, 256>>>(start, B, total);
    prep_bnd_kernel<<<B, 256>>>(lf1, lf2, w1, b1, lens, maxlen, E, H);

    // Stage 1: O1 = Xprev@W1_0 + X@W1_1 + b1   (M=total, N=H, K=E)
    {
        dim3 grid(H / 256, (total + 127) / 128);
        conv_tc<false><<<grid, 512, DYN_SMEM>>>(pXh, pBXh,
                                                pW1f, (size_t)H * E,
                                                b1, nullptr, start,
                                                total, H, E,
                                                nullptr, pO1h);
    }
    // Stage 2: pre = O1prev@W2_0 + O1@W2_1 + b2 + x (M=total, N=E, K=H)
    {
        dim3 grid(E / 256, (total + 127) / 128);
        conv_tc<true><<<grid, 512, DYN_SMEM>>>(pO1h, pBOh,
                                               pW2f, (size_t)E * H,
                                               b2, inputs, start,
                                               total, E, H,
                                               pPre, nullptr);
    }
    rmsnorm_kernel<<<total, 256>>>(pPre, gamma, out, E, 1.f / (float)E);
    lf_kernel<<<B, 256>>>(inputs, start, lens, B, E, H, total,
                          out, (long long)out_size);
}

// round 6
// speedup vs baseline: 6.7317x; 1.0078x over previous
#include <cuda_runtime.h>
#include <cuda_fp16.h>
#include <cstdint>

// ---------------------------------------------------------------------------
// LocalizedFiltering via shifted-pair GEMMs on mma.sync fp16 tensor cores.
//   O1[t] = W1_0 @ xprev(t) + W1_1 @ x[t] + b1
//   pre[t]= W2_0 @ o1prev(t)+ W2_1 @ O1[t]+ b2 + x[t]
//   out[t]= RMSNorm(pre[t]) * gamma
// Precision: single fp16 A and W, fp32 accumulate (2 products per output).
// Pipeline: 4-stage cp.async ring (wait_group 2), BM=128 BN=256 BK=16,
// 256 threads / 8 warps with 64x64 warp tiles (minimizes ldsm bytes/MAC).
// Output: [lf_output total*E][lf1 B*E][lf2 B*H]
// ---------------------------------------------------------------------------

#define MAX_TOTAL 24576
#define MAX_E     2048
#define MAX_H     1024
#define MAX_B     64

#define A_TILE   4096          // 128 rows * 32B
#define B_TILE   8192          // 256 rows * 32B
#define B_OFF    8192          // 2 A tiles
#define STAGE    24576
#define NSTAGE   4
#define DYN_SMEM (STAGE * NSTAGE)

// scratch (static __device__; no cudaMalloc allowed)
__device__ __half g_Xh [(size_t)MAX_TOTAL * MAX_E];
__device__ __half g_O1h[(size_t)MAX_TOTAL * MAX_H];
__device__ __half g_W1f[(size_t)2 * MAX_H * MAX_E]; // [var][n*E+k]
__device__ __half g_W2f[(size_t)2 * MAX_E * MAX_H]; // [var][n*H+k]
__device__ float  g_pre[(size_t)MAX_TOTAL * MAX_E];
__device__ __half g_bndXh[MAX_B * MAX_E];
__device__ __half g_bndOh[MAX_B * MAX_H];
__device__ int    g_tokseq[MAX_TOTAL];

// ---------------------------------------------------------------------------
// helpers
// ---------------------------------------------------------------------------
__device__ __forceinline__ uint32_t smem_u32(const void* p) {
    return (uint32_t)__cvta_generic_to_shared(p);
}
__device__ __forceinline__ void cp16(uint32_t dst, const void* src) {
    asm volatile("cp.async.cg.shared.global [%0], [%1], 16;" :: "r"(dst), "l"(src) : "memory");
}
__device__ __forceinline__ void cp_commit() {
    asm volatile("cp.async.commit_group;" ::: "memory");
}
__device__ __forceinline__ void cp_wait2() {
    asm volatile("cp.async.wait_group 2;" ::: "memory");
}
__device__ __forceinline__ void ldsm_x4(uint32_t* r, uint32_t a) {
    asm volatile("ldmatrix.sync.aligned.m8n8.x4.shared.b16 {%0,%1,%2,%3}, [%4];"
                 : "=r"(r[0]), "=r"(r[1]), "=r"(r[2]), "=r"(r[3]) : "r"(a));
}
__device__ __forceinline__ void mma_fp16(float* c, const uint32_t* a, const uint32_t* b) {
    asm volatile("mma.sync.aligned.m16n8k16.row.col.f32.f16.f16.f32 "
                 "{%0,%1,%2,%3}, {%4,%5,%6,%7}, {%8,%9}, {%0,%1,%2,%3};"
                 : "+f"(c[0]), "+f"(c[1]), "+f"(c[2]), "+f"(c[3])
                 : "r"(a[0]), "r"(a[1]), "r"(a[2]), "r"(a[3]), "r"(b[0]), "r"(b[1]));
}
// smem byte offset within a tile for (row, half16B) with bank-decorrelating XOR
__device__ __forceinline__ uint32_t swz(int row, int half) {
    return (uint32_t)(row * 32 + ((half ^ ((row >> 2) & 1)) << 4));
}

// ---------------------------------------------------------------------------
// prep kernels
// ---------------------------------------------------------------------------
__global__ void split_x_kernel(const float* __restrict__ x, size_t n)
{
    size_t i = ((size_t)blockIdx.x * blockDim.x + threadIdx.x) * 4;
    size_t stride = (size_t)gridDim.x * blockDim.x * 4;
    for (; i < n; i += stride) {
        float4 v = *(const float4*)(x + i);
        *(__half2*)(g_Xh + i)     = __floats2half2_rn(v.x, v.y);
        *(__half2*)(g_Xh + i + 2) = __floats2half2_rn(v.z, v.w);
    }
}

__global__ void pack_w_kernel(const float* __restrict__ w1,
                              const float* __restrict__ w2, int E, int H)
{
    size_t stride = (size_t)gridDim.x * blockDim.x;
    size_t i0 = (size_t)blockIdx.x * blockDim.x + threadIdx.x;
    size_t n1 = (size_t)H * E;
    for (size_t i = i0; i < n1; i += stride) {
        g_W1f[i]      = __float2half_rn(w1[i * 2]);
        g_W1f[n1 + i] = __float2half_rn(w1[i * 2 + 1]);
    }
    size_t n2 = (size_t)E * H;
    for (size_t i = i0; i < n2; i += stride) {
        g_W2f[i]      = __float2half_rn(w2[i * 2]);
        g_W2f[n2 + i] = __float2half_rn(w2[i * 2 + 1]);
    }
}

__global__ void prep_tok_kernel(const int* __restrict__ start, int B, int total)
{
    int t = blockIdx.x * blockDim.x + threadIdx.x;
    if (t >= total) return;
    int lo = 0, hi = B - 1;
    while (lo < hi) {
        int mid = (lo + hi + 1) >> 1;
        if (start[mid] <= t) lo = mid; else hi = mid - 1;
    }
    g_tokseq[t] = lo;
}

__global__ void prep_bnd_kernel(const float* __restrict__ lf1,
                                const float* __restrict__ lf2,
                                const float* __restrict__ w1,
                                const float* __restrict__ b1,
                                const int*   __restrict__ lens,
                                const int*   __restrict__ maxlen_ptr,
                                int E, int H)
{
    int b = blockIdx.x;
    int L = lens[b];
    int ml = maxlen_ptr ? maxlen_ptr[0] : 4096;
    bool full = (L == ml);
    for (int i = threadIdx.x; i < E; i += blockDim.x) {
        float v = full ? lf1[(size_t)b * E + i] : 0.f;
        g_bndXh[(size_t)b * E + i] = __float2half_rn(v);
    }
    int s0 = ml - L;
    for (int n = threadIdx.x; n < H; n += blockDim.x) {
        float v;
        if (full) {
            v = lf2[(size_t)b * H + n];
        } else {
            v = b1[n];
            if (s0 == 1) {
                const float* wr = w1 + (size_t)n * E * 2;
                float acc = 0.f;
                for (int k = 0; k < E; k++) acc += wr[(size_t)k * 2] * lf1[(size_t)b * E + k];
                v += acc;
            }
        }
        g_bndOh[(size_t)b * H + n] = __float2half_rn(v);
    }
}

// ---------------------------------------------------------------------------
// Shifted-pair fp16 GEMM. BM=128 BN=256 BK=16, 256 threads (8 warps, 64x64).
// A variants in smem: 0=prev 1=cur; B variants: 0=W0 1=W1.
// ---------------------------------------------------------------------------
template<bool STAGE2>
__global__ __launch_bounds__(256, 1)
void conv_tc(const __half* __restrict__ srcH,
             const __half* __restrict__ bndH,
             const __half* __restrict__ Wf, size_t wvar,
             const float* __restrict__ bias,
             const float* __restrict__ resid,
             const int* __restrict__ start,
             int M, int Nfull, int K,
             float* __restrict__ outF,
             __half* __restrict__ outH)
{
    extern __shared__ char sm[];
    const uint32_t sbase = smem_u32(sm);
    const int tid = threadIdx.x;
    const int lane = tid & 31;
    const int wid = tid >> 5;
    const int m0 = blockIdx.y * 128;
    const int n0 = blockIdx.x * 256;

    // ---- cp.async slots: 2 A slots + 4 B slots per thread ------------------
    const __half* asrc[2]; uint32_t adst[2];
    #pragma unroll
    for (int i = 0; i < 2; i++) {
        int s = tid + i * 256;
        int var = s >> 8;            // 0=prev 1=cur
        int rem = s & 255;
        int row = rem >> 1;
        int half = rem & 1;
        int t = m0 + row; if (t >= M) t = M - 1;
        const __half* arr;
        if (var == 0) {
            int b = g_tokseq[t];
            arr = (t == start[b]) ? (bndH + (size_t)b * K)
                                  : (srcH + (size_t)(t - 1) * K);
        } else {
            arr = srcH + (size_t)t * K;
        }
        asrc[i] = arr + half * 8;
        adst[i] = (uint32_t)(var * A_TILE) + swz(row, half);
    }
    const __half* bsrc[4]; uint32_t bdst[4];
    #pragma unroll
    for (int i = 0; i < 4; i++) {
        int s = tid + i * 256;
        int var = s >> 9;
        int rem = s & 511;
        int n = rem >> 1;
        int half = rem & 1;
        bsrc[i] = Wf + (size_t)var * wvar + (size_t)(n0 + n) * K + half * 8;
        bdst[i] = (uint32_t)(B_OFF + var * B_TILE) + swz(n, half);
    }

    // ---- mma lane constants: 8 warps, 2 m-bands x 4 n-bands of 64x64 -------
    const int wm = wid & 1;
    const int wn = wid >> 1;            // 0..3
    const int mbase = wm * 64;
    const int nbase = wn * 64;
    const int a_row_off = ((lane >> 3) & 1) * 8 + (lane & 7);
    const int a_kh = lane >> 4;
    const int b_row_off = ((lane >> 4) & 1) * 8 + (lane & 7);
    const int b_h = (lane >> 3) & 1;

    float acc[4][8][4];
    #pragma unroll
    for (int mi = 0; mi < 4; mi++)
        #pragma unroll
        for (int ni = 0; ni < 8; ni++)
            #pragma unroll
            for (int e = 0; e < 4; e++) acc[mi][ni][e] = 0.f;

    auto issue = [&](int it) {
        uint32_t sb = sbase + (it & (NSTAGE - 1)) * STAGE;
        cp16(sb + adst[0], asrc[0] + it * 16);
        cp16(sb + adst[1], asrc[1] + it * 16);
        #pragma unroll
        for (int i = 0; i < 4; i++)
            cp16(sb + bdst[i], bsrc[i] + it * 16);
        cp_commit();
    };

    const int niter = K >> 4;
    issue(0); issue(1); issue(2);

    for (int it = 0; it < niter; ++it) {
        cp_wait2();               // groups <= it complete
        __syncthreads();          // all warps done with the slot being refilled
        if (it + 3 < niter) issue(it + 3);
        else cp_commit();         // empty group keeps count uniform

        const uint32_t base = sbase + (it & (NSTAGE - 1)) * STAGE;
        // B fragments: 2 variants x 4 ldsm_x4 covering 64 n
        uint32_t bb[2][16];
        #pragma unroll
        for (int v = 0; v < 2; v++)
            #pragma unroll
            for (int g = 0; g < 4; g++) {
                int row = nbase + g * 16 + b_row_off;
                ldsm_x4(&bb[v][g * 4], base + B_OFF + v * B_TILE + swz(row, b_h));
            }
        #pragma unroll
        for (int av = 0; av < 2; av++) {
            uint32_t a[4][4];
            #pragma unroll
            for (int mi = 0; mi < 4; mi++) {
                int r = mbase + mi * 16 + a_row_off;
                ldsm_x4(a[mi], base + av * A_TILE + swz(r, a_kh));
            }
            #pragma unroll
            for (int ni = 0; ni < 8; ni++)
                #pragma unroll
                for (int mi = 0; mi < 4; mi++)
                    mma_fp16(acc[mi][ni], a[mi], &bb[av][ni * 2]);
        }
    }

    // ---- epilogue ----------------------------------------------------------
    const int erow = lane >> 2;
    const int ecol = (lane & 3) * 2;
    #pragma unroll
    for (int mi = 0; mi < 4; mi++) {
        int r0 = m0 + mbase + mi * 16 + erow;
        int r1 = r0 + 8;
        #pragma unroll
        for (int ni = 0; ni < 8; ni++) {
            int c = n0 + nbase + ni * 8 + ecol;
            float bx = bias[c], by = bias[c + 1];
            float v00 = acc[mi][ni][0] + bx, v01 = acc[mi][ni][1] + by;
            float v10 = acc[mi][ni][2] + bx, v11 = acc[mi][ni][3] + by;
            if (STAGE2) {
                if (r0 < M) {
                    float2 rr = *(const float2*)(resid + (size_t)r0 * Nfull + c);
                    *(float2*)(outF + (size_t)r0 * Nfull + c) =
                        make_float2(v00 + rr.x, v01 + rr.y);
                }
                if (r1 < M) {
                    float2 rr = *(const float2*)(resid + (size_t)r1 * Nfull + c);
                    *(float2*)(outF + (size_t)r1 * Nfull + c) =
                        make_float2(v10 + rr.x, v11 + rr.y);
                }
            } else {
                if (r0 < M)
                    *(__half2*)(outH + (size_t)r0 * Nfull + c) = __floats2half2_rn(v00, v01);
                if (r1 < M)
                    *(__half2*)(outH + (size_t)r1 * Nfull + c) = __floats2half2_rn(v10, v11);
            }
        }
    }
}

// ---------------------------------------------------------------------------
__global__ __launch_bounds__(256)
void rmsnorm_kernel(const float* __restrict__ pre,
                    const float* __restrict__ gamma,
                    float* __restrict__ out, int E, float invE)
{
    int t = blockIdx.x;
    const float* row = pre + (size_t)t * E;
    float ss = 0.f;
    for (int i = threadIdx.x * 4; i < E; i += blockDim.x * 4) {
        float4 v = *(const float4*)(row + i);
        ss += v.x * v.x + v.y * v.y + v.z * v.z + v.w * v.w;
    }
    __shared__ float red[32];
    #pragma unroll
    for (int o = 16; o; o >>= 1) ss += __shfl_xor_sync(~0u, ss, o);
    if ((threadIdx.x & 31) == 0) red[threadIdx.x >> 5] = ss;
    __syncthreads();
    if (threadIdx.x < 32) {
        float v = (threadIdx.x < (blockDim.x >> 5)) ? red[threadIdx.x] : 0.f;
        #pragma unroll
        for (int o = 16; o; o >>= 1) v += __shfl_xor_sync(~0u, v, o);
        if (threadIdx.x == 0) red[0] = v;
    }
    __syncthreads();
    float scale = rsqrtf(red[0] * invE + 1e-6f);
    for (int i = threadIdx.x * 4; i < E; i += blockDim.x * 4) {
        float4 v = *(const float4*)(row + i);
        float4 g = *(const float4*)(gamma + i);
        v.x *= scale * g.x; v.y *= scale * g.y;
        v.z *= scale * g.z; v.w *= scale * g.w;
        *(float4*)(out + (size_t)t * E + i) = v;
    }
}

__global__ void lf_kernel(const float* __restrict__ inputs,
                          const int* __restrict__ start,
                          const int* __restrict__ lens,
                          int B, int E, int H, int total,
                          float* __restrict__ out, long long out_size)
{
    int b = blockIdx.x;
    int last = start[b] + lens[b] - 1;
    long long base1 = (long long)total * E;
    long long base2 = base1 + (long long)B * E;
    for (int i = threadIdx.x; i < E; i += blockDim.x) {
        long long o = base1 + (long long)b * E + i;
        if (o < out_size) out[o] = inputs[(size_t)last * E + i];
    }
    for (int n = threadIdx.x; n < H; n += blockDim.x) {
        long long o = base2 + (long long)b * H + n;
        if (o < out_size) out[o] = __half2float(g_O1h[(size_t)last * H + n]);
    }
}

__global__ void fallback_kernel(float* out, int n) {
    int i = blockIdx.x * blockDim.x + threadIdx.x;
    if (i < n) out[i] = 0.f;
}

// ---------------------------------------------------------------------------
extern "C" void kernel_launch(void* const* d_in, const int* in_sizes, int n_in,
                              void* d_out, int out_size)
{
    const float* inputs = (const float*)d_in[0];
    const float* lf1    = (const float*)d_in[1];
    const float* lf2    = (const float*)d_in[2];
    const float* w1     = (const float*)d_in[3];
    const float* b1     = (const float*)d_in[4];
    const float* w2     = (const float*)d_in[5];
    const float* b2     = (const float*)d_in[6];
    const float* gamma  = (const float*)d_in[7];
    const int*   start  = (const int*)d_in[8];
    const int*   lens   = (const int*)d_in[9];
    const int*   maxlen = (n_in > 10) ? (const int*)d_in[10] : nullptr;

    const int E = in_sizes[7];
    const int H = in_sizes[4];
    const int total = in_sizes[0] / E;
    const int B = in_sizes[9];
    float* out = (float*)d_out;

    if (E > MAX_E || H > MAX_H || total > MAX_TOTAL || B > MAX_B ||
        (E & 255) || (H & 255)) {
        fallback_kernel<<<(out_size + 255) / 256, 256>>>(out, out_size);
        return;
    }

    __half *pXh, *pO1h, *pW1f, *pW2f, *pBXh, *pBOh;
    float *pPre;
    cudaGetSymbolAddress((void**)&pXh,  g_Xh);
    cudaGetSymbolAddress((void**)&pO1h, g_O1h);
    cudaGetSymbolAddress((void**)&pW1f, g_W1f);
    cudaGetSymbolAddress((void**)&pW2f, g_W2f);
    cudaGetSymbolAddress((void**)&pBXh, g_bndXh);
    cudaGetSymbolAddress((void**)&pBOh, g_bndOh);
    cudaGetSymbolAddress((void**)&pPre, g_pre);

    cudaFuncSetAttribute(conv_tc<false>, cudaFuncAttributeMaxDynamicSharedMemorySize, DYN_SMEM);
    cudaFuncSetAttribute(conv_tc<true>,  cudaFuncAttributeMaxDynamicSharedMemorySize, DYN_SMEM);

    split_x_kernel<<<512, 256>>>(inputs, (size_t)total * E);
    pack_w_kernel<<<512, 256>>>(w1, w2, E, H);
    prep_tok_kernel<<<(total + 255) / 256, 256>>>(start, B, total);
    prep_bnd_kernel<<<B, 256>>>(lf1, lf2, w1, b1, lens, maxlen, E, H);

    // Stage 1: O1 = Xprev@W1_0 + X@W1_1 + b1   (M=total, N=H, K=E)
    {
        dim3 grid(H / 256, (total + 127) / 128);
        conv_tc<false><<<grid, 256, DYN_SMEM>>>(pXh, pBXh,
                                                pW1f, (size_t)H * E,
                                                b1, nullptr, start,
                                                total, H, E,
                                                nullptr, pO1h);
    }
    // Stage 2: pre = O1prev@W2_0 + O1@W2_1 + b2 + x (M=total, N=E, K=H)
    {
        dim3 grid(E / 256, (total + 127) / 128);
        conv_tc<true><<<grid, 256, DYN_SMEM>>>(pO1h, pBOh,
                                               pW2f, (size_t)E * H,
                                               b2, inputs, start,
                                               total, E, H,
                                               pPre, nullptr);
    }
    rmsnorm_kernel<<<total, 256>>>(pPre, gamma, out, E, 1.f / (float)E);
    lf_kernel<<<B, 256>>>(inputs, start, lens, B, E, H, total,
                          out, (long long)out_size);
}

// round 7
// speedup vs baseline: 8.4123x; 1.2497x over previous
#include <cuda_runtime.h>
#include <cuda_fp16.h>
#include <cstdint>

// ---------------------------------------------------------------------------
// LocalizedFiltering via shifted-pair GEMMs on mma.sync fp16 tensor cores.
//   O1[t] = W1_0 @ xprev(t) + W1_1 @ x[t] + b1
//   pre[t]= W2_0 @ o1prev(t)+ W2_1 @ O1[t]+ b2 + x[t]
//   out[t]= RMSNorm(pre[t]) * gamma
// Precision: single fp16 A and W, fp32 accumulate (2 products per output).
// Pipeline: BK=32, 3-stage cp.async ring (wait_group 1), BM=128 BN=256,
// 256 threads / 8 warps with 64x64 warp tiles. 128 mma between syncs.
// Output: [lf_output total*E][lf1 B*E][lf2 B*H]
// ---------------------------------------------------------------------------

#define MAX_TOTAL 24576
#define MAX_E     2048
#define MAX_H     1024
#define MAX_B     64

#define A_TILE   8192          // 128 rows * 64B (per variant)
#define B_OFF    16384         // 2 A tiles
#define B_TILE   16384         // 256 rows * 64B (per variant)
#define STAGE    49152
#define NSTAGE   3
#define DYN_SMEM (STAGE * NSTAGE)

// scratch (static __device__; no cudaMalloc allowed)
__device__ __half g_Xh [(size_t)MAX_TOTAL * MAX_E];
__device__ __half g_O1h[(size_t)MAX_TOTAL * MAX_H];
__device__ __half g_W1f[(size_t)2 * MAX_H * MAX_E]; // [var][n*E+k]
__device__ __half g_W2f[(size_t)2 * MAX_E * MAX_H]; // [var][n*H+k]
__device__ float  g_pre[(size_t)MAX_TOTAL * MAX_E];
__device__ __half g_bndXh[MAX_B * MAX_E];
__device__ __half g_bndOh[MAX_B * MAX_H];
__device__ int    g_tokseq[MAX_TOTAL];

// ---------------------------------------------------------------------------
// helpers
// ---------------------------------------------------------------------------
__device__ __forceinline__ uint32_t smem_u32(const void* p) {
    return (uint32_t)__cvta_generic_to_shared(p);
}
__device__ __forceinline__ void cp16(uint32_t dst, const void* src) {
    asm volatile("cp.async.cg.shared.global [%0], [%1], 16;" :: "r"(dst), "l"(src) : "memory");
}
__device__ __forceinline__ void cp_commit() {
    asm volatile("cp.async.commit_group;" ::: "memory");
}
__device__ __forceinline__ void cp_wait1() {
    asm volatile("cp.async.wait_group 1;" ::: "memory");
}
__device__ __forceinline__ void ldsm_x4(uint32_t* r, uint32_t a) {
    asm volatile("ldmatrix.sync.aligned.m8n8.x4.shared.b16 {%0,%1,%2,%3}, [%4];"
                 : "=r"(r[0]), "=r"(r[1]), "=r"(r[2]), "=r"(r[3]) : "r"(a));
}
__device__ __forceinline__ void mma_fp16(float* c, const uint32_t* a, const uint32_t* b) {
    asm volatile("mma.sync.aligned.m16n8k16.row.col.f32.f16.f16.f32 "
                 "{%0,%1,%2,%3}, {%4,%5,%6,%7}, {%8,%9}, {%0,%1,%2,%3};"
                 : "+f"(c[0]), "+f"(c[1]), "+f"(c[2]), "+f"(c[3])
                 : "r"(a[0]), "r"(a[1]), "r"(a[2]), "r"(a[3]), "r"(b[0]), "r"(b[1]));
}
// 64B-row tile: byte offset for (row, chunk[0..3]) conflict-free for 8-row ldsm
__device__ __forceinline__ uint32_t swz64(int row, int chunk) {
    return (uint32_t)(row * 64 + ((chunk ^ ((row >> 1) & 3)) << 4));
}

// ---------------------------------------------------------------------------
// prep kernels
// ---------------------------------------------------------------------------
__global__ void split_x_kernel(const float* __restrict__ x, size_t n)
{
    size_t i = ((size_t)blockIdx.x * blockDim.x + threadIdx.x) * 4;
    size_t stride = (size_t)gridDim.x * blockDim.x * 4;
    for (; i < n; i += stride) {
        float4 v = *(const float4*)(x + i);
        *(__half2*)(g_Xh + i)     = __floats2half2_rn(v.x, v.y);
        *(__half2*)(g_Xh + i + 2) = __floats2half2_rn(v.z, v.w);
    }
}

__global__ void pack_w_kernel(const float* __restrict__ w1,
                              const float* __restrict__ w2, int E, int H)
{
    size_t stride = (size_t)gridDim.x * blockDim.x;
    size_t i0 = (size_t)blockIdx.x * blockDim.x + threadIdx.x;
    size_t n1 = (size_t)H * E;
    for (size_t i = i0; i < n1; i += stride) {
        g_W1f[i]      = __float2half_rn(w1[i * 2]);
        g_W1f[n1 + i] = __float2half_rn(w1[i * 2 + 1]);
    }
    size_t n2 = (size_t)E * H;
    for (size_t i = i0; i < n2; i += stride) {
        g_W2f[i]      = __float2half_rn(w2[i * 2]);
        g_W2f[n2 + i] = __float2half_rn(w2[i * 2 + 1]);
    }
}

__global__ void prep_tok_kernel(const int* __restrict__ start, int B, int total)
{
    int t = blockIdx.x * blockDim.x + threadIdx.x;
    if (t >= total) return;
    int lo = 0, hi = B - 1;
    while (lo < hi) {
        int mid = (lo + hi + 1) >> 1;
        if (start[mid] <= t) lo = mid; else hi = mid - 1;
    }
    g_tokseq[t] = lo;
}

__global__ void prep_bnd_kernel(const float* __restrict__ lf1,
                                const float* __restrict__ lf2,
                                const float* __restrict__ w1,
                                const float* __restrict__ b1,
                                const int*   __restrict__ lens,
                                const int*   __restrict__ maxlen_ptr,
                                int E, int H)
{
    int b = blockIdx.x;
    int L = lens[b];
    int ml = maxlen_ptr ? maxlen_ptr[0] : 4096;
    bool full = (L == ml);
    for (int i = threadIdx.x; i < E; i += blockDim.x) {
        float v = full ? lf1[(size_t)b * E + i] : 0.f;
        g_bndXh[(size_t)b * E + i] = __float2half_rn(v);
    }
    int s0 = ml - L;
    for (int n = threadIdx.x; n < H; n += blockDim.x) {
        float v;
        if (full) {
            v = lf2[(size_t)b * H + n];
        } else {
            v = b1[n];
            if (s0 == 1) {
                const float* wr = w1 + (size_t)n * E * 2;
                float acc = 0.f;
                for (int k = 0; k < E; k++) acc += wr[(size_t)k * 2] * lf1[(size_t)b * E + k];
                v += acc;
            }
        }
        g_bndOh[(size_t)b * H + n] = __float2half_rn(v);
    }
}

// ---------------------------------------------------------------------------
// Shifted-pair fp16 GEMM. BM=128 BN=256 BK=32, 256 threads (8 warps, 64x64).
// A variants in smem: 0=prev 1=cur; B variants: 0=W0 1=W1.
// ---------------------------------------------------------------------------
template<bool STAGE2>
__global__ __launch_bounds__(256, 1)
void conv_tc(const __half* __restrict__ srcH,
             const __half* __restrict__ bndH,
             const __half* __restrict__ Wf, size_t wvar,
             const float* __restrict__ bias,
             const float* __restrict__ resid,
             const int* __restrict__ start,
             int M, int Nfull, int K,
             float* __restrict__ outF,
             __half* __restrict__ outH)
{
    extern __shared__ char sm[];
    const uint32_t sbase = smem_u32(sm);
    const int tid = threadIdx.x;
    const int lane = tid & 31;
    const int wid = tid >> 5;
    const int m0 = blockIdx.y * 128;
    const int n0 = blockIdx.x * 256;

    // ---- cp.async slots: 4 A chunks + 8 B chunks per thread (16B each) -----
    // A: 2 variants x 128 rows x 4 chunks = 1024 chunks
    const __half* asrc[4]; uint32_t adst[4];
    #pragma unroll
    for (int i = 0; i < 4; i++) {
        int s = tid + i * 256;
        int var = s >> 9;            // 0=prev 1=cur
        int rem = s & 511;
        int row = rem >> 2;
        int c   = rem & 3;
        int t = m0 + row; if (t >= M) t = M - 1;
        const __half* arr;
        if (var == 0) {
            int b = g_tokseq[t];
            arr = (t == start[b]) ? (bndH + (size_t)b * K)
                                  : (srcH + (size_t)(t - 1) * K);
        } else {
            arr = srcH + (size_t)t * K;
        }
        asrc[i] = arr + c * 8;
        adst[i] = (uint32_t)(var * A_TILE) + swz64(row, c);
    }
    // B: 2 variants x 256 rows x 4 chunks = 2048 chunks (32-bit elem offsets)
    uint32_t boff[8]; uint32_t bdst[8];
    #pragma unroll
    for (int i = 0; i < 8; i++) {
        int s = tid + i * 256;
        int var = s >> 10;
        int rem = s & 1023;
        int n = rem >> 2;
        int c = rem & 3;
        boff[i] = (uint32_t)((size_t)var * wvar + (size_t)(n0 + n) * K + c * 8);
        bdst[i] = (uint32_t)(B_OFF + var * B_TILE) + swz64(n, c);
    }

    // ---- mma lane constants: 8 warps, 2 m-bands x 4 n-bands of 64x64 -------
    const int wm = wid & 1;
    const int wn = wid >> 1;
    const int mbase = wm * 64;
    const int nbase = wn * 64;
    const int a_row_off = ((lane >> 3) & 1) * 8 + (lane & 7);
    const int a_kh = lane >> 4;           // 0..1 within a 16-k step
    const int b_row_off = ((lane >> 4) & 1) * 8 + (lane & 7);
    const int b_h = (lane >> 3) & 1;

    float acc[4][8][4];
    #pragma unroll
    for (int mi = 0; mi < 4; mi++)
        #pragma unroll
        for (int ni = 0; ni < 8; ni++)
            #pragma unroll
            for (int e = 0; e < 4; e++) acc[mi][ni][e] = 0.f;

    auto issue = [&](int it) {
        uint32_t sb = sbase + (it % NSTAGE) * STAGE;
        int koff = it * 32;
        #pragma unroll
        for (int i = 0; i < 4; i++)
            cp16(sb + adst[i], asrc[i] + koff);
        #pragma unroll
        for (int i = 0; i < 8; i++)
            cp16(sb + bdst[i], Wf + boff[i] + koff);
        cp_commit();
    };

    const int niter = K >> 5;
    issue(0); issue(1);

    for (int it = 0; it < niter; ++it) {
        cp_wait1();               // group it complete
        __syncthreads();          // slot (it+2)%NSTAGE free (used by it-1)
        if (it + 2 < niter) issue(it + 2);
        else cp_commit();         // empty group keeps count uniform

        const uint32_t base = sbase + (it % NSTAGE) * STAGE;
        #pragma unroll
        for (int ks = 0; ks < 2; ks++) {
            // B fragments: 2 variants x 4 ldsm_x4 covering 64 n, this k-step
            uint32_t bb[2][16];
            #pragma unroll
            for (int v = 0; v < 2; v++)
                #pragma unroll
                for (int g = 0; g < 4; g++) {
                    int row = nbase + g * 16 + b_row_off;
                    ldsm_x4(&bb[v][g * 4],
                            base + B_OFF + v * B_TILE + swz64(row, ks * 2 + b_h));
                }
            #pragma unroll
            for (int av = 0; av < 2; av++) {
                uint32_t a[4][4];
                #pragma unroll
                for (int mi = 0; mi < 4; mi++) {
                    int r = mbase + mi * 16 + a_row_off;
                    ldsm_x4(a[mi], base + av * A_TILE + swz64(r, ks * 2 + a_kh));
                }
                #pragma unroll
                for (int ni = 0; ni < 8; ni++)
                    #pragma unroll
                    for (int mi = 0; mi < 4; mi++)
                        mma_fp16(acc[mi][ni], a[mi], &bb[av][ni * 2]);
            }
        }
    }

    // ---- epilogue ----------------------------------------------------------
    const int erow = lane >> 2;
    const int ecol = (lane & 3) * 2;
    #pragma unroll
    for (int mi = 0; mi < 4; mi++) {
        int r0 = m0 + mbase + mi * 16 + erow;
        int r1 = r0 + 8;
        #pragma unroll
        for (int ni = 0; ni < 8; ni++) {
            int c = n0 + nbase + ni * 8 + ecol;
            float bx = bias[c], by = bias[c + 1];
            float v00 = acc[mi][ni][0] + bx, v01 = acc[mi][ni][1] + by;
            float v10 = acc[mi][ni][2] + bx, v11 = acc[mi][ni][3] + by;
            if (STAGE2) {
                if (r0 < M) {
                    float2 rr = *(const float2*)(resid + (size_t)r0 * Nfull + c);
                    *(float2*)(outF + (size_t)r0 * Nfull + c) =
                        make_float2(v00 + rr.x, v01 + rr.y);
                }
                if (r1 < M) {
                    float2 rr = *(const float2*)(resid + (size_t)r1 * Nfull + c);
                    *(float2*)(outF + (size_t)r1 * Nfull + c) =
                        make_float2(v10 + rr.x, v11 + rr.y);
                }
            } else {
                if (r0 < M)
                    *(__half2*)(outH + (size_t)r0 * Nfull + c) = __floats2half2_rn(v00, v01);
                if (r1 < M)
                    *(__half2*)(outH + (size_t)r1 * Nfull + c) = __floats2half2_rn(v10, v11);
            }
        }
    }
}

// ---------------------------------------------------------------------------
__global__ __launch_bounds__(256)
void rmsnorm_kernel(const float* __restrict__ pre,
                    const float* __restrict__ gamma,
                    float* __restrict__ out, int E, float invE)
{
    int t = blockIdx.x;
    const float* row = pre + (size_t)t * E;
    float ss = 0.f;
    for (int i = threadIdx.x * 4; i < E; i += blockDim.x * 4) {
        float4 v = *(const float4*)(row + i);
        ss += v.x * v.x + v.y * v.y + v.z * v.z + v.w * v.w;
    }
    __shared__ float red[32];
    #pragma unroll
    for (int o = 16; o; o >>= 1) ss += __shfl_xor_sync(~0u, ss, o);
    if ((threadIdx.x & 31) == 0) red[threadIdx.x >> 5] = ss;
    __syncthreads();
    if (threadIdx.x < 32) {
        float v = (threadIdx.x < (blockDim.x >> 5)) ? red[threadIdx.x] : 0.f;
        #pragma unroll
        for (int o = 16; o; o >>= 1) v += __shfl_xor_sync(~0u, v, o);
        if (threadIdx.x == 0) red[0] = v;
    }
    __syncthreads();
    float scale = rsqrtf(red[0] * invE + 1e-6f);
    for (int i = threadIdx.x * 4; i < E; i += blockDim.x * 4) {
        float4 v = *(const float4*)(row + i);
        float4 g = *(const float4*)(gamma + i);
        v.x *= scale * g.x; v.y *= scale * g.y;
        v.z *= scale * g.z; v.w *= scale * g.w;
        *(float4*)(out + (size_t)t * E + i) = v;
    }
}

__global__ void lf_kernel(const float* __restrict__ inputs,
                          const int* __restrict__ start,
                          const int* __restrict__ lens,
                          int B, int E, int H, int total,
                          float* __restrict__ out, long long out_size)
{
    int b = blockIdx.x;
    int last = start[b] + lens[b] - 1;
    long long base1 = (long long)total * E;
    long long base2 = base1 + (long long)B * E;
    for (int i = threadIdx.x; i < E; i += blockDim.x) {
        long long o = base1 + (long long)b * E + i;
        if (o < out_size) out[o] = inputs[(size_t)last * E + i];
    }
    for (int n = threadIdx.x; n < H; n += blockDim.x) {
        long long o = base2 + (long long)b * H + n;
        if (o < out_size) out[o] = __half2float(g_O1h[(size_t)last * H + n]);
    }
}

__global__ void fallback_kernel(float* out, int n) {
    int i = blockIdx.x * blockDim.x + threadIdx.x;
    if (i < n) out[i] = 0.f;
}

// ---------------------------------------------------------------------------
extern "C" void kernel_launch(void* const* d_in, const int* in_sizes, int n_in,
                              void* d_out, int out_size)
{
    const float* inputs = (const float*)d_in[0];
    const float* lf1    = (const float*)d_in[1];
    const float* lf2    = (const float*)d_in[2];
    const float* w1     = (const float*)d_in[3];
    const float* b1     = (const float*)d_in[4];
    const float* w2     = (const float*)d_in[5];
    const float* b2     = (const float*)d_in[6];
    const float* gamma  = (const float*)d_in[7];
    const int*   start  = (const int*)d_in[8];
    const int*   lens   = (const int*)d_in[9];
    const int*   maxlen = (n_in > 10) ? (const int*)d_in[10] : nullptr;

    const int E = in_sizes[7];
    const int H = in_sizes[4];
    const int total = in_sizes[0] / E;
    const int B = in_sizes[9];
    float* out = (float*)d_out;

    if (E > MAX_E || H > MAX_H || total > MAX_TOTAL || B > MAX_B ||
        (E & 255) || (H & 255) || (E & 31) || (H & 31)) {
        fallback_kernel<<<(out_size + 255) / 256, 256>>>(out, out_size);
        return;
    }

    __half *pXh, *pO1h, *pW1f, *pW2f, *pBXh, *pBOh;
    float *pPre;
    cudaGetSymbolAddress((void**)&pXh,  g_Xh);
    cudaGetSymbolAddress((void**)&pO1h, g_O1h);
    cudaGetSymbolAddress((void**)&pW1f, g_W1f);
    cudaGetSymbolAddress((void**)&pW2f, g_W2f);
    cudaGetSymbolAddress((void**)&pBXh, g_bndXh);
    cudaGetSymbolAddress((void**)&pBOh, g_bndOh);
    cudaGetSymbolAddress((void**)&pPre, g_pre);

    cudaFuncSetAttribute(conv_tc<false>, cudaFuncAttributeMaxDynamicSharedMemorySize, DYN_SMEM);
    cudaFuncSetAttribute(conv_tc<true>,  cudaFuncAttributeMaxDynamicSharedMemorySize, DYN_SMEM);

    split_x_kernel<<<512, 256>>>(inputs, (size_t)total * E);
    pack_w_kernel<<<512, 256>>>(w1, w2, E, H);
    prep_tok_kernel<<<(total + 255) / 256, 256>>>(start, B, total);
    prep_bnd_kernel<<<B, 256>>>(lf1, lf2, w1, b1, lens, maxlen, E, H);

    // Stage 1: O1 = Xprev@W1_0 + X@W1_1 + b1   (M=total, N=H, K=E)
    {
        dim3 grid(H / 256, (total + 127) / 128);
        conv_tc<false><<<grid, 256, DYN_SMEM>>>(pXh, pBXh,
                                                pW1f, (size_t)H * E,
                                                b1, nullptr, start,
                                                total, H, E,
                                                nullptr, pO1h);
    }
    // Stage 2: pre = O1prev@W2_0 + O1@W2_1 + b2 + x (M=total, N=E, K=H)
    {
        dim3 grid(E / 256, (total + 127) / 128);
        conv_tc<true><<<grid, 256, DYN_SMEM>>>(pO1h, pBOh,
                                               pW2f, (size_t)E * H,
                                               b2, inputs, start,
                                               total, E, H,
                                               pPre, nullptr);
    }
    rmsnorm_kernel<<<total, 256>>>(pPre, gamma, out, E, 1.f / (float)E);
    lf_kernel<<<B, 256>>>(inputs, start, lens, B, E, H, total,
                          out, (long long)out_size);
}